// round 4
// baseline (speedup 1.0000x reference)
#include <cuda_runtime.h>
#include <math.h>
#include <stdint.h>

#define DIM     1024
#define TLEN    16384
#define WIN     32
#define DH      64
#define HEADS   16
#define NWIN    (TLEN / WIN)      // 512
#define QKV_N   (3 * DIM)         // 3072

// K-group permutation: original col c (within 8-group) stored at position 2*(c&3)+(c>>2)
#define KPERM8(j)  ((((j) & 3) << 1) | (((j) >> 2) & 1))

// ---------------- scratch (static device globals; no allocation) ----------------
static __device__ float g_normed[(size_t)TLEN * DIM];    // (T, C) tf32-rounded, K-permuted
static __device__ float g_qkv[(size_t)TLEN * QKV_N];     // (T, 3C) fp32 (not permuted)
static __device__ float g_attn[(size_t)TLEN * DIM];      // (T, C) tf32-rounded, K-permuted
static __device__ float g_wqkv_r[(size_t)QKV_N * DIM];   // tf32-rounded, K-permuted
static __device__ float g_wout_r[(size_t)DIM * DIM];     // tf32-rounded, K-permuted

// =============================== helpers ===================================
__device__ __forceinline__ uint32_t smem_u32(const void* p) {
    uint32_t a;
    asm("{ .reg .u64 t; cvta.to.shared.u64 t, %1; cvt.u32.u64 %0, t; }" : "=r"(a) : "l"(p));
    return a;
}
__device__ __forceinline__ float rna_tf32(float x) {
    uint32_t r;
    asm("cvt.rna.tf32.f32 %0, %1;" : "=r"(r) : "f"(x));
    return __uint_as_float(r);
}

// =================================================================================
// Kernel 0: round fp32 -> tf32 representable, store K-permuted (last dim = K)
// =================================================================================
__global__ void round_tf32_perm_kernel(const float* __restrict__ in, float* __restrict__ out, int n)
{
    int i = blockIdx.x * blockDim.x + threadIdx.x;
    if (i < n) {
        int p = (i & ~7) | KPERM8(i & 7);
        out[p] = rna_tf32(in[i]);
    }
}

// =================================================================================
// Kernel 1: LayerNorm over channels + transpose (C,T) -> (T,C)
// single-pass (register-cached x), tf32-rounded + K-permuted output
// =================================================================================
__global__ void __launch_bounds__(1024) ln_transpose_kernel(
    const float* __restrict__ x,
    const float* __restrict__ gamma,
    const float* __restrict__ beta)
{
    __shared__ float reds[32][33];
    __shared__ float redq[32][33];
    __shared__ __align__(16) float tile[32][33];
    __shared__ float s_mean[32], s_rstd[32];

    const int tx = threadIdx.x;   // token within tile on load
    const int ty = threadIdx.y;   // channel within chunk
    const int t0 = blockIdx.x * 32;

    float cache[32];
    float sum = 0.f, sumsq = 0.f;
    #pragma unroll
    for (int ci = 0; ci < 32; ci++) {
        float v = x[(size_t)(ci * 32 + ty) * TLEN + t0 + tx];
        cache[ci] = v;
        sum += v;
        sumsq += v * v;
    }
    reds[ty][tx] = sum;
    redq[ty][tx] = sumsq;
    __syncthreads();
    for (int s = 16; s > 0; s >>= 1) {
        if (ty < s) {
            reds[ty][tx] += reds[ty + s][tx];
            redq[ty][tx] += redq[ty + s][tx];
        }
        __syncthreads();
    }
    if (ty == 0) {
        float m = reds[0][tx] * (1.0f / DIM);
        float var = redq[0][tx] * (1.0f / DIM) - m * m;
        s_mean[tx] = m;
        s_rstd[tx] = rsqrtf(var + 1e-5f);
    }
    __syncthreads();

    const int wtx = (tx & 24) | KPERM8(tx & 7);   // permuted channel-within-32
    #pragma unroll
    for (int ci = 0; ci < 32; ci++) {
        int c0 = ci * 32;
        float nv = (cache[ci] - s_mean[tx]) * s_rstd[tx] * gamma[c0 + ty] + beta[c0 + ty];
        tile[ty][tx] = nv;
        __syncthreads();
        // thread (tx,ty) writes channel c0+tx (permuted) of token t0+ty
        g_normed[(size_t)(t0 + ty) * DIM + c0 + wtx] = rna_tf32(tile[tx][ty]);
        __syncthreads();
    }
}

// =================================================================================
// Kernel 2: mma.sync tf32 GEMM-NT on K-permuted operands: C = A * B^T (+resid)
// BM=BN=128, BK=32, 3-stage cp.async, 256 threads (8 warps, 64x32 tiles).
// Vectorized conflict-free LDS.64 fragment loads + register double-buffering.
// =================================================================================
#define GBM 128
#define GBN 128
#define GBK 32
#define GSTAGES 3
#define ROWF 36
#define TILEF (128 * ROWF)
#define STAGEF (2 * TILEF)
#define GSMEM_BYTES (GSTAGES * STAGEF * 4)   // 110592 B

template <bool RESID>
__global__ void __launch_bounds__(256, 2) mma_gemm_nt(
    const float* __restrict__ A,
    const float* __restrict__ B,
    float* __restrict__ C,
    const float* __restrict__ resid,
    int M, int N, int K)
{
    extern __shared__ float sm[];
    const uint32_t sb = smem_u32(sm);
    const int tid  = threadIdx.x;
    const int wid  = tid >> 5;
    const int lane = tid & 31;
    const int g = lane >> 2;          // 0..7
    const int t = lane & 3;           // 0..3
    const int pg = KPERM8(g);         // physical row offset within 8-group
    const int m0 = blockIdx.y * GBM;
    const int n0 = blockIdx.x * GBN;
    const int wm = (wid >> 2) * 64;
    const int wn = (wid & 3) * 32;
    const int KC = K / GBK;

    // loader coords: idx = tid + i*256 -> logical row (idx>>3), chunk (idx&7)
    const int lrow0 = tid >> 3;                  // 0..31
    const int lc4   = (tid & 7) << 2;            // float offset 0..28
    const int prow0 = (lrow0 & ~7) | KPERM8(lrow0 & 7);   // physical row base

    float c[4][4][4];
    #pragma unroll
    for (int mi = 0; mi < 4; mi++)
        #pragma unroll
        for (int ni = 0; ni < 4; ni++)
            #pragma unroll
            for (int j = 0; j < 4; j++) c[mi][ni][j] = 0.f;

    // prologue: stages 0,1
    #pragma unroll
    for (int s = 0; s < GSTAGES - 1; s++) {
        uint32_t ab = sb + 4u * (uint32_t)(s * STAGEF);
        #pragma unroll
        for (int i = 0; i < 4; i++) {
            int lrow = lrow0 + i * 32;
            int prow = prow0 + i * 32;
            uint32_t sa = ab + 4u * (uint32_t)(prow * ROWF + lc4);
            const float* ga = A + (size_t)(m0 + lrow) * K + s * GBK + lc4;
            asm volatile("cp.async.cg.shared.global [%0], [%1], 16;" :: "r"(sa), "l"(ga));
            uint32_t sbb = sa + 4u * TILEF;
            const float* gb = B + (size_t)(n0 + lrow) * K + s * GBK + lc4;
            asm volatile("cp.async.cg.shared.global [%0], [%1], 16;" :: "r"(sbb), "l"(gb));
        }
        asm volatile("cp.async.commit_group;");
    }

    // per-thread fragment base offsets (bytes, within a stage)
    const uint32_t a_base_off = 4u * (uint32_t)((wm + pg) * ROWF + 2 * t);
    const uint32_t b_base_off = 4u * (uint32_t)(TILEF + (wn + pg) * ROWF + 2 * t);

    float2 alo[2][4], ahi[2][4], bf[2][4];

#define LD_FRAG(buf, stg_addr, kkf)  do {                                         \
        uint32_t _ka = (stg_addr) + a_base_off + 4u * (uint32_t)(kkf);            \
        uint32_t _kb = (stg_addr) + b_base_off + 4u * (uint32_t)(kkf);            \
        _Pragma("unroll")                                                          \
        for (int mi = 0; mi < 4; mi++) {                                           \
            uint32_t aa = _ka + 4u * (uint32_t)(mi * 16 * ROWF);                   \
            asm volatile("ld.shared.v2.f32 {%0,%1}, [%2];"                        \
                : "=f"(alo[buf][mi].x), "=f"(alo[buf][mi].y) : "r"(aa));          \
            asm volatile("ld.shared.v2.f32 {%0,%1}, [%2];"                        \
                : "=f"(ahi[buf][mi].x), "=f"(ahi[buf][mi].y)                      \
                : "r"(aa + 4u * (uint32_t)(8 * ROWF)));                            \
        }                                                                          \
        _Pragma("unroll")                                                          \
        for (int ni = 0; ni < 4; ni++) {                                           \
            uint32_t bb = _kb + 4u * (uint32_t)(ni * 8 * ROWF);                    \
            asm volatile("ld.shared.v2.f32 {%0,%1}, [%2];"                        \
                : "=f"(bf[buf][ni].x), "=f"(bf[buf][ni].y) : "r"(bb));            \
        }                                                                          \
    } while (0)

#define DO_MMA(buf)  do {                                                          \
        _Pragma("unroll")                                                          \
        for (int mi = 0; mi < 4; mi++) {                                           \
            uint32_t a0 = __float_as_uint(alo[buf][mi].x);                         \
            uint32_t a1 = __float_as_uint(ahi[buf][mi].x);                         \
            uint32_t a2 = __float_as_uint(alo[buf][mi].y);                         \
            uint32_t a3 = __float_as_uint(ahi[buf][mi].y);                         \
            _Pragma("unroll")                                                      \
            for (int ni = 0; ni < 4; ni++) {                                       \
                asm volatile(                                                      \
                    "mma.sync.aligned.m16n8k8.row.col.f32.tf32.tf32.f32 "          \
                    "{%0,%1,%2,%3},{%4,%5,%6,%7},{%8,%9},{%0,%1,%2,%3};"           \
                    : "+f"(c[mi][ni][0]), "+f"(c[mi][ni][1]),                      \
                      "+f"(c[mi][ni][2]), "+f"(c[mi][ni][3])                       \
                    : "r"(a0), "r"(a1), "r"(a2), "r"(a3),                          \
                      "r"(__float_as_uint(bf[buf][ni].x)),                         \
                      "r"(__float_as_uint(bf[buf][ni].y)));                        \
            }                                                                      \
        }                                                                          \
    } while (0)

    for (int kc = 0; kc < KC; kc++) {
        if (kc + 1 < KC) asm volatile("cp.async.wait_group 1;");
        else             asm volatile("cp.async.wait_group 0;");
        __syncthreads();

        // issue loads for chunk kc+2 into slot (kc+2)%3
        int nxt = kc + 2;
        if (nxt < KC) {
            int slot = nxt % GSTAGES;
            uint32_t ab = sb + 4u * (uint32_t)(slot * STAGEF);
            #pragma unroll
            for (int i = 0; i < 4; i++) {
                int lrow = lrow0 + i * 32;
                int prow = prow0 + i * 32;
                uint32_t sa = ab + 4u * (uint32_t)(prow * ROWF + lc4);
                const float* ga = A + (size_t)(m0 + lrow) * K + nxt * GBK + lc4;
                asm volatile("cp.async.cg.shared.global [%0], [%1], 16;" :: "r"(sa), "l"(ga));
                uint32_t sbb = sa + 4u * TILEF;
                const float* gb = B + (size_t)(n0 + lrow) * K + nxt * GBK + lc4;
                asm volatile("cp.async.cg.shared.global [%0], [%1], 16;" :: "r"(sbb), "l"(gb));
            }
            asm volatile("cp.async.commit_group;");
        }

        const uint32_t stg = sb + 4u * (uint32_t)((kc % GSTAGES) * STAGEF);

        LD_FRAG(0, stg, 0);
        LD_FRAG(1, stg, 8);
        DO_MMA(0);
        LD_FRAG(0, stg, 16);
        DO_MMA(1);
        LD_FRAG(1, stg, 24);
        DO_MMA(0);
        DO_MMA(1);
    }

    // epilogue: thread (g,t) owns rows (wm+16mi+g, +8), cols (wn+8ni+2t, +1)
    #pragma unroll
    for (int mi = 0; mi < 4; mi++) {
        #pragma unroll
        for (int ni = 0; ni < 4; ni++) {
            size_t r0  = (size_t)(m0 + wm + mi * 16 + g);
            size_t col = (size_t)(n0 + wn + ni * 8 + 2 * t);
            size_t off0 = r0 * N + col;
            size_t off1 = (r0 + 8) * N + col;
            float2 v0 = make_float2(c[mi][ni][0], c[mi][ni][1]);
            float2 v1 = make_float2(c[mi][ni][2], c[mi][ni][3]);
            if (RESID) {
                float2 rv0 = *(const float2*)&resid[off0];
                float2 rv1 = *(const float2*)&resid[off1];
                v0.x += rv0.x; v0.y += rv0.y;
                v1.x += rv1.x; v1.y += rv1.y;
            }
            *(float2*)&C[off0] = v0;
            *(float2*)&C[off1] = v1;
        }
    }
#undef LD_FRAG
#undef DO_MMA
}

// =================================================================================
// Kernel 3: per (head, window) attention with RoPE (fp32),
// tf32-rounded + K-permuted output (channel dim permuted within 8-groups)
// =================================================================================
__global__ void __launch_bounds__(256) attn_kernel()
{
    __shared__ __align__(16) float q[32][68];
    __shared__ __align__(16) float k[32][68];
    __shared__ __align__(16) float v[32][68];
    __shared__ float p[32][33];

    const int w = blockIdx.x;
    const int h = blockIdx.y;
    const int tid = threadIdx.x;

    const float* base = g_qkv + (size_t)w * WIN * QKV_N + h * DH;

    #pragma unroll
    for (int it = 0; it < 2; it++) {
        int idx = tid + it * 256;
        int n   = idx >> 4;
        int d4  = (idx & 15) << 2;
        const float* rowp = base + (size_t)n * QKV_N + d4;
        *(float4*)&q[n][d4] = *(const float4*)(rowp);
        *(float4*)&k[n][d4] = *(const float4*)(rowp + DIM);
        *(float4*)&v[n][d4] = *(const float4*)(rowp + 2 * DIM);
    }
    __syncthreads();

    #pragma unroll
    for (int it = 0; it < 4; it++) {
        int idx = tid + it * 256;
        int n = idx >> 5;
        int i = idx & 31;
        float invf = expf(-logf(10000.f) * (float)i * (1.0f / 32.0f));
        float ang  = (float)n * invf;
        float c = cosf(ang), s = sinf(ang);
        float qa = q[n][i], qb = q[n][i + 32];
        q[n][i]      = qa * c - qb * s;
        q[n][i + 32] = qb * c + qa * s;
        float ka = k[n][i], kb = k[n][i + 32];
        k[n][i]      = ka * c - kb * s;
        k[n][i + 32] = kb * c + ka * s;
    }
    __syncthreads();

    {
        int i  = tid >> 3;
        int j0 = (tid & 7) << 2;
        float s0 = 0.f, s1 = 0.f, s2 = 0.f, s3 = 0.f;
        #pragma unroll
        for (int d = 0; d < DH; d++) {
            float qv = q[i][d];
            s0 = fmaf(qv, k[j0 + 0][d], s0);
            s1 = fmaf(qv, k[j0 + 1][d], s1);
            s2 = fmaf(qv, k[j0 + 2][d], s2);
            s3 = fmaf(qv, k[j0 + 3][d], s3);
        }
        const float scale = 0.125f;
        p[i][j0 + 0] = s0 * scale;
        p[i][j0 + 1] = s1 * scale;
        p[i][j0 + 2] = s2 * scale;
        p[i][j0 + 3] = s3 * scale;
    }
    __syncthreads();

    {
        int warp = tid >> 5, lane = tid & 31;
        for (int r = warp; r < 32; r += 8) {
            float val = p[r][lane];
            float m = val;
            #pragma unroll
            for (int o = 16; o > 0; o >>= 1)
                m = fmaxf(m, __shfl_xor_sync(0xFFFFFFFFu, m, o));
            float e = expf(val - m);
            float sum = e;
            #pragma unroll
            for (int o = 16; o > 0; o >>= 1)
                sum += __shfl_xor_sync(0xFFFFFFFFu, sum, o);
            p[r][lane] = e / sum;
        }
    }
    __syncthreads();

    {
        int oi = tid >> 3;
        int d0 = (tid & 7) << 3;
        float o[8];
        #pragma unroll
        for (int dd = 0; dd < 8; dd++) o[dd] = 0.f;
        #pragma unroll
        for (int j = 0; j < 32; j++) {
            float pv = p[oi][j];
            #pragma unroll
            for (int dd = 0; dd < 8; dd++)
                o[dd] = fmaf(pv, v[j][d0 + dd], o[dd]);
        }
        // write permuted within the 8-group: pos[p] = o[j] where KPERM8(j)=p
        float* outp = g_attn + (size_t)(w * WIN + oi) * DIM + h * DH + d0;
        float4 o0, o1;
        o0.x = rna_tf32(o[0]); o0.y = rna_tf32(o[4]);
        o0.z = rna_tf32(o[1]); o0.w = rna_tf32(o[5]);
        o1.x = rna_tf32(o[2]); o1.y = rna_tf32(o[6]);
        o1.z = rna_tf32(o[3]); o1.w = rna_tf32(o[7]);
        *(float4*)(outp)     = o0;
        *(float4*)(outp + 4) = o1;
    }
}

// =================================================================================
// launch
// =================================================================================
extern "C" void kernel_launch(void* const* d_in, const int* in_sizes, int n_in,
                              void* d_out, int out_size)
{
    (void)in_sizes; (void)n_in; (void)out_size;
    const float* x     = (const float*)d_in[0];
    const float* w_qkv = (const float*)d_in[1];
    const float* w_out = (const float*)d_in[2];
    const float* gamma = (const float*)d_in[3];
    const float* beta  = (const float*)d_in[4];
    float* out = (float*)d_out;

    float *normed, *qkv, *attn, *wqkv_r, *wout_r;
    cudaGetSymbolAddress((void**)&normed, g_normed);
    cudaGetSymbolAddress((void**)&qkv,    g_qkv);
    cudaGetSymbolAddress((void**)&attn,   g_attn);
    cudaGetSymbolAddress((void**)&wqkv_r, g_wqkv_r);
    cudaGetSymbolAddress((void**)&wout_r, g_wout_r);

    cudaFuncSetAttribute(mma_gemm_nt<false>, cudaFuncAttributeMaxDynamicSharedMemorySize, GSMEM_BYTES);
    cudaFuncSetAttribute(mma_gemm_nt<true>,  cudaFuncAttributeMaxDynamicSharedMemorySize, GSMEM_BYTES);

    // 0) round weights to tf32-representable, K-permuted
    round_tf32_perm_kernel<<<(QKV_N * DIM + 255) / 256, 256>>>(w_qkv, wqkv_r, QKV_N * DIM);
    round_tf32_perm_kernel<<<(DIM * DIM + 255) / 256, 256>>>(w_out, wout_r, DIM * DIM);

    // 1) LayerNorm + transpose -> g_normed (T, C), tf32-rounded, K-permuted
    ln_transpose_kernel<<<TLEN / 32, dim3(32, 32)>>>(x, gamma, beta);

    // 2) QKV GEMM (tf32 mma.sync): (T,3C) = normed @ w_qkv^T
    mma_gemm_nt<false><<<dim3(QKV_N / GBN, TLEN / GBM), 256, GSMEM_BYTES>>>(
        normed, wqkv_r, qkv, nullptr, TLEN, QKV_N, DIM);

    // 3) windowed RoPE attention -> g_attn (T, C), tf32-rounded, K-permuted
    attn_kernel<<<dim3(NWIN, HEADS), 256>>>();

    // 4) out = (w_out @ attn^T) + x, written directly as (C, T)
    mma_gemm_nt<true><<<dim3(TLEN / GBN, DIM / GBM), 256, GSMEM_BYTES>>>(
        wout_r, attn, out, x, DIM, TLEN, DIM);
}

// round 5
// speedup vs baseline: 1.0030x; 1.0030x over previous
#include <cuda_runtime.h>
#include <math.h>
#include <stdint.h>

#define DIM     1024
#define TLEN    16384
#define WIN     32
#define DH      64
#define HEADS   16
#define NWIN    (TLEN / WIN)      // 512
#define QKV_N   (3 * DIM)         // 3072

// ---------------- scratch (static device globals; no allocation) ----------------
static __device__ float g_normed[(size_t)TLEN * DIM];    // (T, C) tf32-rounded
static __device__ float g_qkv[(size_t)TLEN * QKV_N];     // (T, 3C) fp32
static __device__ float g_attn[(size_t)TLEN * DIM];      // (T, C) tf32-rounded
static __device__ float g_wqkv_r[(size_t)QKV_N * DIM];   // tf32-rounded weights
static __device__ float g_wout_r[(size_t)DIM * DIM];     // tf32-rounded weights
static __device__ float g_rope_cos[WIN * 32];            // cos table (pos, pair)
static __device__ float g_rope_sin[WIN * 32];            // sin table (pos, pair)

// =============================== helpers ===================================
__device__ __forceinline__ uint32_t smem_u32(const void* p) {
    uint32_t a;
    asm("{ .reg .u64 t; cvta.to.shared.u64 t, %1; cvt.u32.u64 %0, t; }" : "=r"(a) : "l"(p));
    return a;
}
__device__ __forceinline__ float rna_tf32(float x) {
    uint32_t r;
    asm("cvt.rna.tf32.f32 %0, %1;" : "=r"(r) : "f"(x));
    return __uint_as_float(r);
}

// =================================================================================
// Kernel 0a: round fp32 -> tf32 representable (removes HW-truncation bias)
// =================================================================================
__global__ void round_tf32_kernel(const float* __restrict__ in, float* __restrict__ out, int n4)
{
    int i = blockIdx.x * blockDim.x + threadIdx.x;
    if (i < n4) {
        float4 v = *(const float4*)&in[i * 4];
        v.x = rna_tf32(v.x); v.y = rna_tf32(v.y);
        v.z = rna_tf32(v.z); v.w = rna_tf32(v.w);
        *(float4*)&out[i * 4] = v;
    }
}

// =================================================================================
// Kernel 0b: RoPE table init (runs once per launch; 1 block, 1024 threads)
// =================================================================================
__global__ void rope_init_kernel()
{
    int idx = threadIdx.x;            // 0..1023
    int n = idx >> 5;                 // position 0..31
    int i = idx & 31;                 // pair index 0..31
    float invf = expf(-logf(10000.f) * (float)i * (1.0f / 32.0f));
    float ang  = (float)n * invf;
    g_rope_cos[idx] = cosf(ang);
    g_rope_sin[idx] = sinf(ang);
}

// =================================================================================
// Kernel 1: LayerNorm over channels + transpose (C,T) -> (T,C)
// single-pass (register-cached x), tf32-rounded output
// =================================================================================
__global__ void __launch_bounds__(1024) ln_transpose_kernel(
    const float* __restrict__ x,
    const float* __restrict__ gamma,
    const float* __restrict__ beta)
{
    __shared__ float reds[32][33];
    __shared__ float redq[32][33];
    __shared__ __align__(16) float tile[32][33];
    __shared__ float s_mean[32], s_rstd[32];

    const int tx = threadIdx.x;   // token within tile on load
    const int ty = threadIdx.y;   // channel within chunk
    const int t0 = blockIdx.x * 32;

    float cache[32];
    float sum = 0.f, sumsq = 0.f;
    #pragma unroll
    for (int ci = 0; ci < 32; ci++) {
        float v = x[(size_t)(ci * 32 + ty) * TLEN + t0 + tx];
        cache[ci] = v;
        sum += v;
        sumsq += v * v;
    }
    reds[ty][tx] = sum;
    redq[ty][tx] = sumsq;
    __syncthreads();
    for (int s = 16; s > 0; s >>= 1) {
        if (ty < s) {
            reds[ty][tx] += reds[ty + s][tx];
            redq[ty][tx] += redq[ty + s][tx];
        }
        __syncthreads();
    }
    if (ty == 0) {
        float m = reds[0][tx] * (1.0f / DIM);
        float var = redq[0][tx] * (1.0f / DIM) - m * m;
        s_mean[tx] = m;
        s_rstd[tx] = rsqrtf(var + 1e-5f);
    }
    __syncthreads();

    #pragma unroll
    for (int ci = 0; ci < 32; ci++) {
        int c0 = ci * 32;
        float nv = (cache[ci] - s_mean[tx]) * s_rstd[tx] * gamma[c0 + ty] + beta[c0 + ty];
        tile[ty][tx] = nv;
        __syncthreads();
        g_normed[(size_t)(t0 + ty) * DIM + c0 + tx] = rna_tf32(tile[tx][ty]);
        __syncthreads();
    }
}

// =================================================================================
// Kernel 2: mma.sync tf32 GEMM-NT: C[M,N] = A[M,K] * B[N,K]^T   (+resid)
// BM=BN=128, BK=32, 3-stage cp.async pipeline, 256 threads (8 warps, 64x32 each).
// =================================================================================
#define GBM 128
#define GBN 128
#define GBK 32
#define GSTAGES 3
#define ROWF 36
#define TILEF (128 * ROWF)
#define STAGEF (2 * TILEF)
#define GSMEM_BYTES (GSTAGES * STAGEF * 4)   // 110592 B

template <bool RESID>
__global__ void __launch_bounds__(256) mma_gemm_nt(
    const float* __restrict__ A,
    const float* __restrict__ B,
    float* __restrict__ C,
    const float* __restrict__ resid,
    int M, int N, int K)
{
    extern __shared__ float sm[];
    const int tid  = threadIdx.x;
    const int wid  = tid >> 5;
    const int lane = tid & 31;
    const int g = lane >> 2;          // 0..7
    const int t = lane & 3;           // 0..3
    const int m0 = blockIdx.y * GBM;
    const int n0 = blockIdx.x * GBN;
    const int wm = (wid >> 2) * 64;   // warp m offset within block
    const int wn = (wid & 3) * 32;    // warp n offset within block
    const int KC = K / GBK;

    float c[4][4][4];
    #pragma unroll
    for (int mi = 0; mi < 4; mi++)
        #pragma unroll
        for (int ni = 0; ni < 4; ni++)
            #pragma unroll
            for (int j = 0; j < 4; j++) c[mi][ni][j] = 0.f;

    // prologue: stages 0 and 1
    #pragma unroll
    for (int s = 0; s < GSTAGES - 1; s++) {
        float* as = sm + s * STAGEF;
        float* bs = as + TILEF;
        #pragma unroll
        for (int i = 0; i < 4; i++) {
            int idx = tid + i * 256;
            int row = idx >> 3;
            int c4  = (idx & 7) << 2;
            uint32_t sa = smem_u32(as + row * ROWF + c4);
            const float* ga = A + (size_t)(m0 + row) * K + s * GBK + c4;
            asm volatile("cp.async.cg.shared.global [%0], [%1], 16;" :: "r"(sa), "l"(ga));
            uint32_t sb = smem_u32(bs + row * ROWF + c4);
            const float* gb = B + (size_t)(n0 + row) * K + s * GBK + c4;
            asm volatile("cp.async.cg.shared.global [%0], [%1], 16;" :: "r"(sb), "l"(gb));
        }
        asm volatile("cp.async.commit_group;");
    }

    for (int kc = 0; kc < KC; kc++) {
        if (kc + 1 < KC) asm volatile("cp.async.wait_group 1;");
        else             asm volatile("cp.async.wait_group 0;");
        __syncthreads();

        int nxt = kc + 2;
        if (nxt < KC) {
            int slot = nxt % GSTAGES;
            float* as = sm + slot * STAGEF;
            float* bs = as + TILEF;
            #pragma unroll
            for (int i = 0; i < 4; i++) {
                int idx = tid + i * 256;
                int row = idx >> 3;
                int c4  = (idx & 7) << 2;
                uint32_t sa = smem_u32(as + row * ROWF + c4);
                const float* ga = A + (size_t)(m0 + row) * K + nxt * GBK + c4;
                asm volatile("cp.async.cg.shared.global [%0], [%1], 16;" :: "r"(sa), "l"(ga));
                uint32_t sb = smem_u32(bs + row * ROWF + c4);
                const float* gb = B + (size_t)(n0 + row) * K + nxt * GBK + c4;
                asm volatile("cp.async.cg.shared.global [%0], [%1], 16;" :: "r"(sb), "l"(gb));
            }
            asm volatile("cp.async.commit_group;");
        }

        const float* as = sm + (kc % GSTAGES) * STAGEF;
        const float* bs = as + TILEF;

        #pragma unroll
        for (int kk = 0; kk < GBK; kk += 8) {
            uint32_t a[4][4], b[4][2];
            #pragma unroll
            for (int mi = 0; mi < 4; mi++) {
                const float* ap = as + (wm + mi * 16 + g) * ROWF + kk + t;
                a[mi][0] = __float_as_uint(ap[0]);
                a[mi][1] = __float_as_uint(ap[8 * ROWF]);
                a[mi][2] = __float_as_uint(ap[4]);
                a[mi][3] = __float_as_uint(ap[8 * ROWF + 4]);
            }
            #pragma unroll
            for (int ni = 0; ni < 4; ni++) {
                const float* bp = bs + (wn + ni * 8 + g) * ROWF + kk + t;
                b[ni][0] = __float_as_uint(bp[0]);
                b[ni][1] = __float_as_uint(bp[4]);
            }
            #pragma unroll
            for (int mi = 0; mi < 4; mi++)
                #pragma unroll
                for (int ni = 0; ni < 4; ni++)
                    asm volatile(
                        "mma.sync.aligned.m16n8k8.row.col.f32.tf32.tf32.f32 "
                        "{%0,%1,%2,%3},{%4,%5,%6,%7},{%8,%9},{%0,%1,%2,%3};"
                        : "+f"(c[mi][ni][0]), "+f"(c[mi][ni][1]),
                          "+f"(c[mi][ni][2]), "+f"(c[mi][ni][3])
                        : "r"(a[mi][0]), "r"(a[mi][1]), "r"(a[mi][2]), "r"(a[mi][3]),
                          "r"(b[ni][0]), "r"(b[ni][1]));
        }
    }

    // epilogue: thread (g,t) owns rows (wm+16mi+g, +8), cols (wn+8ni+2t, +1)
    #pragma unroll
    for (int mi = 0; mi < 4; mi++) {
        #pragma unroll
        for (int ni = 0; ni < 4; ni++) {
            size_t r0  = (size_t)(m0 + wm + mi * 16 + g);
            size_t col = (size_t)(n0 + wn + ni * 8 + 2 * t);
            size_t off0 = r0 * N + col;
            size_t off1 = (r0 + 8) * N + col;
            float2 v0 = make_float2(c[mi][ni][0], c[mi][ni][1]);
            float2 v1 = make_float2(c[mi][ni][2], c[mi][ni][3]);
            if (RESID) {
                float2 rv0 = *(const float2*)&resid[off0];
                float2 rv1 = *(const float2*)&resid[off1];
                v0.x += rv0.x; v0.y += rv0.y;
                v1.x += rv1.x; v1.y += rv1.y;
            }
            *(float2*)&C[off0] = v0;
            *(float2*)&C[off1] = v1;
        }
    }
}

// =================================================================================
// Kernel 3: per (head, window) attention with RoPE (fp32), tf32-rounded output.
// RoPE cos/sin from precomputed global table; fast-math softmax.
// =================================================================================
__global__ void __launch_bounds__(256) attn_kernel()
{
    __shared__ __align__(16) float q[32][68];
    __shared__ __align__(16) float k[32][68];
    __shared__ __align__(16) float v[32][68];
    __shared__ float p[32][33];

    const int w = blockIdx.x;
    const int h = blockIdx.y;
    const int tid = threadIdx.x;

    const float* base = g_qkv + (size_t)w * WIN * QKV_N + h * DH;

    #pragma unroll
    for (int it = 0; it < 2; it++) {
        int idx = tid + it * 256;
        int n   = idx >> 4;
        int d4  = (idx & 15) << 2;
        const float* rowp = base + (size_t)n * QKV_N + d4;
        *(float4*)&q[n][d4] = *(const float4*)(rowp);
        *(float4*)&k[n][d4] = *(const float4*)(rowp + DIM);
        *(float4*)&v[n][d4] = *(const float4*)(rowp + 2 * DIM);
    }
    __syncthreads();

    // RoPE via precomputed tables: 1024 (pos,pair) entries, 4 per thread
    #pragma unroll
    for (int it = 0; it < 4; it++) {
        int idx = tid + it * 256;       // 0..1023 == n*32 + i
        int n = idx >> 5;
        int i = idx & 31;
        float c = g_rope_cos[idx];
        float s = g_rope_sin[idx];
        float qa = q[n][i], qb = q[n][i + 32];
        q[n][i]      = qa * c - qb * s;
        q[n][i + 32] = qb * c + qa * s;
        float ka = k[n][i], kb = k[n][i + 32];
        k[n][i]      = ka * c - kb * s;
        k[n][i + 32] = kb * c + ka * s;
    }
    __syncthreads();

    {
        int i  = tid >> 3;
        int j0 = (tid & 7) << 2;
        float s0 = 0.f, s1 = 0.f, s2 = 0.f, s3 = 0.f;
        #pragma unroll
        for (int d = 0; d < DH; d++) {
            float qv = q[i][d];
            s0 = fmaf(qv, k[j0 + 0][d], s0);
            s1 = fmaf(qv, k[j0 + 1][d], s1);
            s2 = fmaf(qv, k[j0 + 2][d], s2);
            s3 = fmaf(qv, k[j0 + 3][d], s3);
        }
        const float scale = 0.125f;
        p[i][j0 + 0] = s0 * scale;
        p[i][j0 + 1] = s1 * scale;
        p[i][j0 + 2] = s2 * scale;
        p[i][j0 + 3] = s3 * scale;
    }
    __syncthreads();

    {
        int warp = tid >> 5, lane = tid & 31;
        for (int r = warp; r < 32; r += 8) {
            float val = p[r][lane];
            float m = val;
            #pragma unroll
            for (int o = 16; o > 0; o >>= 1)
                m = fmaxf(m, __shfl_xor_sync(0xFFFFFFFFu, m, o));
            float e = __expf(val - m);
            float sum = e;
            #pragma unroll
            for (int o = 16; o > 0; o >>= 1)
                sum += __shfl_xor_sync(0xFFFFFFFFu, sum, o);
            p[r][lane] = __fdividef(e, sum);
        }
    }
    __syncthreads();

    {
        int oi = tid >> 3;
        int d0 = (tid & 7) << 3;
        float o[8];
        #pragma unroll
        for (int dd = 0; dd < 8; dd++) o[dd] = 0.f;
        #pragma unroll
        for (int j = 0; j < 32; j++) {
            float pv = p[oi][j];
            #pragma unroll
            for (int dd = 0; dd < 8; dd++)
                o[dd] = fmaf(pv, v[j][d0 + dd], o[dd]);
        }
        float* outp = g_attn + (size_t)(w * WIN + oi) * DIM + h * DH + d0;
        float4 o0, o1;
        o0.x = rna_tf32(o[0]); o0.y = rna_tf32(o[1]);
        o0.z = rna_tf32(o[2]); o0.w = rna_tf32(o[3]);
        o1.x = rna_tf32(o[4]); o1.y = rna_tf32(o[5]);
        o1.z = rna_tf32(o[6]); o1.w = rna_tf32(o[7]);
        *(float4*)(outp)     = o0;
        *(float4*)(outp + 4) = o1;
    }
}

// =================================================================================
// launch
// =================================================================================
extern "C" void kernel_launch(void* const* d_in, const int* in_sizes, int n_in,
                              void* d_out, int out_size)
{
    (void)in_sizes; (void)n_in; (void)out_size;
    const float* x     = (const float*)d_in[0];
    const float* w_qkv = (const float*)d_in[1];
    const float* w_out = (const float*)d_in[2];
    const float* gamma = (const float*)d_in[3];
    const float* beta  = (const float*)d_in[4];
    float* out = (float*)d_out;

    float *normed, *qkv, *attn, *wqkv_r, *wout_r;
    cudaGetSymbolAddress((void**)&normed, g_normed);
    cudaGetSymbolAddress((void**)&qkv,    g_qkv);
    cudaGetSymbolAddress((void**)&attn,   g_attn);
    cudaGetSymbolAddress((void**)&wqkv_r, g_wqkv_r);
    cudaGetSymbolAddress((void**)&wout_r, g_wout_r);

    cudaFuncSetAttribute(mma_gemm_nt<false>, cudaFuncAttributeMaxDynamicSharedMemorySize, GSMEM_BYTES);
    cudaFuncSetAttribute(mma_gemm_nt<true>,  cudaFuncAttributeMaxDynamicSharedMemorySize, GSMEM_BYTES);

    // 0) round weights to tf32-representable; init RoPE tables
    round_tf32_kernel<<<(QKV_N * DIM / 4 + 255) / 256, 256>>>(w_qkv, wqkv_r, QKV_N * DIM / 4);
    round_tf32_kernel<<<(DIM * DIM / 4 + 255) / 256, 256>>>(w_out, wout_r, DIM * DIM / 4);
    rope_init_kernel<<<1, 1024>>>();

    // 1) LayerNorm + transpose -> g_normed (T, C), tf32-rounded
    ln_transpose_kernel<<<TLEN / 32, dim3(32, 32)>>>(x, gamma, beta);

    // 2) QKV GEMM (tf32 mma.sync): (T,3C) = normed @ w_qkv^T
    mma_gemm_nt<false><<<dim3(QKV_N / GBN, TLEN / GBM), 256, GSMEM_BYTES>>>(
        normed, wqkv_r, qkv, nullptr, TLEN, QKV_N, DIM);

    // 3) windowed RoPE attention -> g_attn (T, C), tf32-rounded
    attn_kernel<<<dim3(NWIN, HEADS), 256>>>();

    // 4) out = (w_out @ attn^T) + x, written directly as (C, T)
    mma_gemm_nt<true><<<dim3(TLEN / GBN, DIM / GBM), 256, GSMEM_BYTES>>>(
        wout_r, attn, out, x, DIM, TLEN, DIM);
}

// round 6
// speedup vs baseline: 1.3148x; 1.3109x over previous
#include <cuda_runtime.h>
#include <math.h>
#include <stdint.h>

#define DIM     1024
#define TLEN    16384
#define WIN     32
#define DH      64
#define HEADS   16
#define NWIN    (TLEN / WIN)      // 512
#define QKV_N   (3 * DIM)         // 3072

// ---------------- scratch (static device globals; no allocation) ----------------
static __device__ float g_normed[(size_t)TLEN * DIM];    // (T, C) tf32-rounded
static __device__ float g_qkv[(size_t)TLEN * QKV_N];     // (T, 3C) fp32
static __device__ float g_attn[(size_t)TLEN * DIM];      // (T, C) tf32-rounded
static __device__ float g_wqkv_r[(size_t)QKV_N * DIM];   // tf32-rounded weights
static __device__ float g_wout_r[(size_t)DIM * DIM];     // tf32-rounded weights
static __device__ float g_rope_cos[WIN * 32];            // cos table (pos, pair)
static __device__ float g_rope_sin[WIN * 32];            // sin table (pos, pair)

// =============================== helpers ===================================
__device__ __forceinline__ uint32_t smem_u32(const void* p) {
    uint32_t a;
    asm("{ .reg .u64 t; cvta.to.shared.u64 t, %1; cvt.u32.u64 %0, t; }" : "=r"(a) : "l"(p));
    return a;
}
__device__ __forceinline__ float rna_tf32(float x) {
    uint32_t r;
    asm("cvt.rna.tf32.f32 %0, %1;" : "=r"(r) : "f"(x));
    return __uint_as_float(r);
}

// =================================================================================
// Kernel 0a: round fp32 -> tf32 representable (removes HW-truncation bias)
// =================================================================================
__global__ void round_tf32_kernel(const float* __restrict__ in, float* __restrict__ out, int n4)
{
    int i = blockIdx.x * blockDim.x + threadIdx.x;
    if (i < n4) {
        float4 v = *(const float4*)&in[i * 4];
        v.x = rna_tf32(v.x); v.y = rna_tf32(v.y);
        v.z = rna_tf32(v.z); v.w = rna_tf32(v.w);
        *(float4*)&out[i * 4] = v;
    }
}

// =================================================================================
// Kernel 0b: RoPE table init
// =================================================================================
__global__ void rope_init_kernel()
{
    int idx = threadIdx.x;            // 0..1023
    int n = idx >> 5;
    int i = idx & 31;
    float invf = expf(-logf(10000.f) * (float)i * (1.0f / 32.0f));
    float ang  = (float)n * invf;
    g_rope_cos[idx] = cosf(ang);
    g_rope_sin[idx] = sinf(ang);
}

// =================================================================================
// Kernel 1: LayerNorm over channels + transpose (C,T) -> (T,C), single-pass
// =================================================================================
__global__ void __launch_bounds__(1024) ln_transpose_kernel(
    const float* __restrict__ x,
    const float* __restrict__ gamma,
    const float* __restrict__ beta)
{
    __shared__ float reds[32][33];
    __shared__ float redq[32][33];
    __shared__ __align__(16) float tile[32][33];
    __shared__ float s_mean[32], s_rstd[32];

    const int tx = threadIdx.x;
    const int ty = threadIdx.y;
    const int t0 = blockIdx.x * 32;

    float cache[32];
    float sum = 0.f, sumsq = 0.f;
    #pragma unroll
    for (int ci = 0; ci < 32; ci++) {
        float v = x[(size_t)(ci * 32 + ty) * TLEN + t0 + tx];
        cache[ci] = v;
        sum += v;
        sumsq += v * v;
    }
    reds[ty][tx] = sum;
    redq[ty][tx] = sumsq;
    __syncthreads();
    for (int s = 16; s > 0; s >>= 1) {
        if (ty < s) {
            reds[ty][tx] += reds[ty + s][tx];
            redq[ty][tx] += redq[ty + s][tx];
        }
        __syncthreads();
    }
    if (ty == 0) {
        float m = reds[0][tx] * (1.0f / DIM);
        float var = redq[0][tx] * (1.0f / DIM) - m * m;
        s_mean[tx] = m;
        s_rstd[tx] = rsqrtf(var + 1e-5f);
    }
    __syncthreads();

    #pragma unroll
    for (int ci = 0; ci < 32; ci++) {
        int c0 = ci * 32;
        float nv = (cache[ci] - s_mean[tx]) * s_rstd[tx] * gamma[c0 + ty] + beta[c0 + ty];
        tile[ty][tx] = nv;
        __syncthreads();
        g_normed[(size_t)(t0 + ty) * DIM + c0 + tx] = rna_tf32(tile[tx][ty]);
        __syncthreads();
    }
}

// =================================================================================
// Kernel 2: mma.sync tf32 GEMM-NT: C[M,N] = A[M,K] * B[N,K]^T   (+resid)
// =================================================================================
#define GBM 128
#define GBN 128
#define GBK 32
#define GSTAGES 3
#define ROWF 36
#define TILEF (128 * ROWF)
#define STAGEF (2 * TILEF)
#define GSMEM_BYTES (GSTAGES * STAGEF * 4)   // 110592 B

template <bool RESID>
__global__ void __launch_bounds__(256) mma_gemm_nt(
    const float* __restrict__ A,
    const float* __restrict__ B,
    float* __restrict__ C,
    const float* __restrict__ resid,
    int M, int N, int K)
{
    extern __shared__ float sm[];
    const int tid  = threadIdx.x;
    const int wid  = tid >> 5;
    const int lane = tid & 31;
    const int g = lane >> 2;
    const int t = lane & 3;
    const int m0 = blockIdx.y * GBM;
    const int n0 = blockIdx.x * GBN;
    const int wm = (wid >> 2) * 64;
    const int wn = (wid & 3) * 32;
    const int KC = K / GBK;

    float c[4][4][4];
    #pragma unroll
    for (int mi = 0; mi < 4; mi++)
        #pragma unroll
        for (int ni = 0; ni < 4; ni++)
            #pragma unroll
            for (int j = 0; j < 4; j++) c[mi][ni][j] = 0.f;

    #pragma unroll
    for (int s = 0; s < GSTAGES - 1; s++) {
        float* as = sm + s * STAGEF;
        float* bs = as + TILEF;
        #pragma unroll
        for (int i = 0; i < 4; i++) {
            int idx = tid + i * 256;
            int row = idx >> 3;
            int c4  = (idx & 7) << 2;
            uint32_t sa = smem_u32(as + row * ROWF + c4);
            const float* ga = A + (size_t)(m0 + row) * K + s * GBK + c4;
            asm volatile("cp.async.cg.shared.global [%0], [%1], 16;" :: "r"(sa), "l"(ga));
            uint32_t sb = smem_u32(bs + row * ROWF + c4);
            const float* gb = B + (size_t)(n0 + row) * K + s * GBK + c4;
            asm volatile("cp.async.cg.shared.global [%0], [%1], 16;" :: "r"(sb), "l"(gb));
        }
        asm volatile("cp.async.commit_group;");
    }

    for (int kc = 0; kc < KC; kc++) {
        if (kc + 1 < KC) asm volatile("cp.async.wait_group 1;");
        else             asm volatile("cp.async.wait_group 0;");
        __syncthreads();

        int nxt = kc + 2;
        if (nxt < KC) {
            int slot = nxt % GSTAGES;
            float* as = sm + slot * STAGEF;
            float* bs = as + TILEF;
            #pragma unroll
            for (int i = 0; i < 4; i++) {
                int idx = tid + i * 256;
                int row = idx >> 3;
                int c4  = (idx & 7) << 2;
                uint32_t sa = smem_u32(as + row * ROWF + c4);
                const float* ga = A + (size_t)(m0 + row) * K + nxt * GBK + c4;
                asm volatile("cp.async.cg.shared.global [%0], [%1], 16;" :: "r"(sa), "l"(ga));
                uint32_t sb = smem_u32(bs + row * ROWF + c4);
                const float* gb = B + (size_t)(n0 + row) * K + nxt * GBK + c4;
                asm volatile("cp.async.cg.shared.global [%0], [%1], 16;" :: "r"(sb), "l"(gb));
            }
            asm volatile("cp.async.commit_group;");
        }

        const float* as = sm + (kc % GSTAGES) * STAGEF;
        const float* bs = as + TILEF;

        #pragma unroll
        for (int kk = 0; kk < GBK; kk += 8) {
            uint32_t a[4][4], b[4][2];
            #pragma unroll
            for (int mi = 0; mi < 4; mi++) {
                const float* ap = as + (wm + mi * 16 + g) * ROWF + kk + t;
                a[mi][0] = __float_as_uint(ap[0]);
                a[mi][1] = __float_as_uint(ap[8 * ROWF]);
                a[mi][2] = __float_as_uint(ap[4]);
                a[mi][3] = __float_as_uint(ap[8 * ROWF + 4]);
            }
            #pragma unroll
            for (int ni = 0; ni < 4; ni++) {
                const float* bp = bs + (wn + ni * 8 + g) * ROWF + kk + t;
                b[ni][0] = __float_as_uint(bp[0]);
                b[ni][1] = __float_as_uint(bp[4]);
            }
            #pragma unroll
            for (int mi = 0; mi < 4; mi++)
                #pragma unroll
                for (int ni = 0; ni < 4; ni++)
                    asm volatile(
                        "mma.sync.aligned.m16n8k8.row.col.f32.tf32.tf32.f32 "
                        "{%0,%1,%2,%3},{%4,%5,%6,%7},{%8,%9},{%0,%1,%2,%3};"
                        : "+f"(c[mi][ni][0]), "+f"(c[mi][ni][1]),
                          "+f"(c[mi][ni][2]), "+f"(c[mi][ni][3])
                        : "r"(a[mi][0]), "r"(a[mi][1]), "r"(a[mi][2]), "r"(a[mi][3]),
                          "r"(b[ni][0]), "r"(b[ni][1]));
        }
    }

    #pragma unroll
    for (int mi = 0; mi < 4; mi++) {
        #pragma unroll
        for (int ni = 0; ni < 4; ni++) {
            size_t r0  = (size_t)(m0 + wm + mi * 16 + g);
            size_t col = (size_t)(n0 + wn + ni * 8 + 2 * t);
            size_t off0 = r0 * N + col;
            size_t off1 = (r0 + 8) * N + col;
            float2 v0 = make_float2(c[mi][ni][0], c[mi][ni][1]);
            float2 v1 = make_float2(c[mi][ni][2], c[mi][ni][3]);
            if (RESID) {
                float2 rv0 = *(const float2*)&resid[off0];
                float2 rv1 = *(const float2*)&resid[off1];
                v0.x += rv0.x; v0.y += rv0.y;
                v1.x += rv1.x; v1.y += rv1.y;
            }
            *(float2*)&C[off0] = v0;
            *(float2*)&C[off1] = v1;
        }
    }
}

// =================================================================================
// Kernel 3: warp-per-(window,head) attention via tf32 mma.sync.
// S = QK^T (64 MMAs), register softmax, PV (64 MMAs). All operands rna-rounded.
// smem per warp: q/k/v 32x68 floats (p aliases q).
// =================================================================================
#define AWARPS 4
#define ASTRIDE 68
#define AWARP_F (3 * 32 * ASTRIDE)                 // floats per warp
#define ASMEM_BYTES (AWARPS * AWARP_F * 4)         // 104448 B

__global__ void __launch_bounds__(AWARPS * 32) attn_mma_kernel()
{
    extern __shared__ float as_[];
    const int lane = threadIdx.x & 31;
    const int wid  = threadIdx.x >> 5;
    const int pair = blockIdx.x * AWARPS + wid;    // 0..8191
    const int w = pair >> 4;
    const int h = pair & 15;
    const int gr = lane >> 2;                      // 0..7
    const int t  = lane & 3;                       // 0..3

    float* q = as_ + wid * AWARP_F;
    float* k = q + 32 * ASTRIDE;
    float* v = k + 32 * ASTRIDE;
    float* p = q;                                  // alias (q dead after S)

    const float* gbase = g_qkv + (size_t)w * WIN * QKV_N + h * DH;

    // ---- stage Q,K,V (V rounded here) ----
    #pragma unroll
    for (int it = 0; it < 16; it++) {
        int idx = lane + it * 32;                  // 0..511
        int n   = idx >> 4;
        int d4  = (idx & 15) << 2;
        const float* rp = gbase + (size_t)n * QKV_N + d4;
        float4 qa = *(const float4*)rp;
        float4 ka = *(const float4*)(rp + DIM);
        float4 va = *(const float4*)(rp + 2 * DIM);
        *(float4*)&q[n * ASTRIDE + d4] = qa;
        *(float4*)&k[n * ASTRIDE + d4] = ka;
        va.x = rna_tf32(va.x); va.y = rna_tf32(va.y);
        va.z = rna_tf32(va.z); va.w = rna_tf32(va.w);
        *(float4*)&v[n * ASTRIDE + d4] = va;
    }
    __syncwarp();

    // ---- RoPE + round on Q,K ----
    #pragma unroll
    for (int it = 0; it < 32; it++) {
        int idx = lane + it * 32;                  // 0..1023
        int n = idx >> 5;
        int i = idx & 31;
        float c = g_rope_cos[idx];
        float s = g_rope_sin[idx];
        float* qr = q + n * ASTRIDE;
        float* kr = k + n * ASTRIDE;
        float qa = qr[i], qb = qr[i + 32];
        qr[i]      = rna_tf32(qa * c - qb * s);
        qr[i + 32] = rna_tf32(qb * c + qa * s);
        float ka = kr[i], kb = kr[i + 32];
        kr[i]      = rna_tf32(ka * c - kb * s);
        kr[i + 32] = rna_tf32(kb * c + ka * s);
    }
    __syncwarp();

    // ---- S = Q K^T : M=32 (2 mtiles), N=32 (4 ntiles), K=64 (8 ksteps) ----
    float s[2][4][4];
    #pragma unroll
    for (int mi = 0; mi < 2; mi++)
        #pragma unroll
        for (int nt = 0; nt < 4; nt++)
            #pragma unroll
            for (int j = 0; j < 4; j++) s[mi][nt][j] = 0.f;

    #pragma unroll
    for (int kk = 0; kk < 64; kk += 8) {
        uint32_t a[2][4], b[4][2];
        #pragma unroll
        for (int mi = 0; mi < 2; mi++) {
            const float* ap = q + (mi * 16 + gr) * ASTRIDE + kk + t;
            a[mi][0] = __float_as_uint(ap[0]);
            a[mi][1] = __float_as_uint(ap[8 * ASTRIDE]);
            a[mi][2] = __float_as_uint(ap[4]);
            a[mi][3] = __float_as_uint(ap[8 * ASTRIDE + 4]);
        }
        #pragma unroll
        for (int nt = 0; nt < 4; nt++) {
            const float* bp = k + (nt * 8 + gr) * ASTRIDE + kk + t;
            b[nt][0] = __float_as_uint(bp[0]);
            b[nt][1] = __float_as_uint(bp[4]);
        }
        #pragma unroll
        for (int mi = 0; mi < 2; mi++)
            #pragma unroll
            for (int nt = 0; nt < 4; nt++)
                asm volatile(
                    "mma.sync.aligned.m16n8k8.row.col.f32.tf32.tf32.f32 "
                    "{%0,%1,%2,%3},{%4,%5,%6,%7},{%8,%9},{%0,%1,%2,%3};"
                    : "+f"(s[mi][nt][0]), "+f"(s[mi][nt][1]),
                      "+f"(s[mi][nt][2]), "+f"(s[mi][nt][3])
                    : "r"(a[mi][0]), "r"(a[mi][1]), "r"(a[mi][2]), "r"(a[mi][3]),
                      "r"(b[nt][0]), "r"(b[nt][1]));
    }
    __syncwarp();   // all q/k reads done before p (aliased to q) is written

    // ---- softmax per row (4 rows per thread), write rounded P to smem ----
    const float scale = 0.125f;
    #pragma unroll
    for (int mi = 0; mi < 2; mi++) {
        #pragma unroll
        for (int half = 0; half < 2; half++) {
            int row = mi * 16 + gr + 8 * half;
            float e[8];
            float m = -1e30f;
            #pragma unroll
            for (int nt = 0; nt < 4; nt++) {
                e[2 * nt]     = s[mi][nt][2 * half]     * scale;
                e[2 * nt + 1] = s[mi][nt][2 * half + 1] * scale;
                m = fmaxf(m, fmaxf(e[2 * nt], e[2 * nt + 1]));
            }
            m = fmaxf(m, __shfl_xor_sync(0xFFFFFFFFu, m, 1));
            m = fmaxf(m, __shfl_xor_sync(0xFFFFFFFFu, m, 2));
            float sum = 0.f;
            #pragma unroll
            for (int j = 0; j < 8; j++) {
                e[j] = __expf(e[j] - m);
                sum += e[j];
            }
            sum += __shfl_xor_sync(0xFFFFFFFFu, sum, 1);
            sum += __shfl_xor_sync(0xFFFFFFFFu, sum, 2);
            float inv = __fdividef(1.0f, sum);
            float* pr = p + row * ASTRIDE + 2 * t;
            #pragma unroll
            for (int nt = 0; nt < 4; nt++) {
                pr[nt * 8]     = rna_tf32(e[2 * nt]     * inv);
                pr[nt * 8 + 1] = rna_tf32(e[2 * nt + 1] * inv);
            }
        }
    }
    __syncwarp();

    // ---- O = P V : M=32 (2 mtiles), N=64 (8 ntiles), K=32 (4 ksteps) ----
    float o[2][8][4];
    #pragma unroll
    for (int mi = 0; mi < 2; mi++)
        #pragma unroll
        for (int nt = 0; nt < 8; nt++)
            #pragma unroll
            for (int j = 0; j < 4; j++) o[mi][nt][j] = 0.f;

    #pragma unroll
    for (int kk = 0; kk < 32; kk += 8) {
        uint32_t a[2][4];
        #pragma unroll
        for (int mi = 0; mi < 2; mi++) {
            const float* ap = p + (mi * 16 + gr) * ASTRIDE + kk + t;
            a[mi][0] = __float_as_uint(ap[0]);
            a[mi][1] = __float_as_uint(ap[8 * ASTRIDE]);
            a[mi][2] = __float_as_uint(ap[4]);
            a[mi][3] = __float_as_uint(ap[8 * ASTRIDE + 4]);
        }
        #pragma unroll
        for (int nt = 0; nt < 8; nt++) {
            uint32_t b0 = __float_as_uint(v[(kk + t) * ASTRIDE + nt * 8 + gr]);
            uint32_t b1 = __float_as_uint(v[(kk + t + 4) * ASTRIDE + nt * 8 + gr]);
            #pragma unroll
            for (int mi = 0; mi < 2; mi++)
                asm volatile(
                    "mma.sync.aligned.m16n8k8.row.col.f32.tf32.tf32.f32 "
                    "{%0,%1,%2,%3},{%4,%5,%6,%7},{%8,%9},{%0,%1,%2,%3};"
                    : "+f"(o[mi][nt][0]), "+f"(o[mi][nt][1]),
                      "+f"(o[mi][nt][2]), "+f"(o[mi][nt][3])
                    : "r"(a[mi][0]), "r"(a[mi][1]), "r"(a[mi][2]), "r"(a[mi][3]),
                      "r"(b0), "r"(b1));
        }
    }

    // ---- store O (rounded) to g_attn (T, C) ----
    float* op = g_attn + (size_t)(w * WIN) * DIM + h * DH;
    #pragma unroll
    for (int mi = 0; mi < 2; mi++) {
        #pragma unroll
        for (int nt = 0; nt < 8; nt++) {
            int row0 = mi * 16 + gr;
            int col  = nt * 8 + 2 * t;
            float2 v0 = make_float2(rna_tf32(o[mi][nt][0]), rna_tf32(o[mi][nt][1]));
            float2 v1 = make_float2(rna_tf32(o[mi][nt][2]), rna_tf32(o[mi][nt][3]));
            *(float2*)&op[(size_t)row0 * DIM + col]       = v0;
            *(float2*)&op[(size_t)(row0 + 8) * DIM + col] = v1;
        }
    }
}

// =================================================================================
// launch
// =================================================================================
extern "C" void kernel_launch(void* const* d_in, const int* in_sizes, int n_in,
                              void* d_out, int out_size)
{
    (void)in_sizes; (void)n_in; (void)out_size;
    const float* x     = (const float*)d_in[0];
    const float* w_qkv = (const float*)d_in[1];
    const float* w_out = (const float*)d_in[2];
    const float* gamma = (const float*)d_in[3];
    const float* beta  = (const float*)d_in[4];
    float* out = (float*)d_out;

    float *normed, *qkv, *attn, *wqkv_r, *wout_r;
    cudaGetSymbolAddress((void**)&normed, g_normed);
    cudaGetSymbolAddress((void**)&qkv,    g_qkv);
    cudaGetSymbolAddress((void**)&attn,   g_attn);
    cudaGetSymbolAddress((void**)&wqkv_r, g_wqkv_r);
    cudaGetSymbolAddress((void**)&wout_r, g_wout_r);

    cudaFuncSetAttribute(mma_gemm_nt<false>, cudaFuncAttributeMaxDynamicSharedMemorySize, GSMEM_BYTES);
    cudaFuncSetAttribute(mma_gemm_nt<true>,  cudaFuncAttributeMaxDynamicSharedMemorySize, GSMEM_BYTES);
    cudaFuncSetAttribute(attn_mma_kernel,    cudaFuncAttributeMaxDynamicSharedMemorySize, ASMEM_BYTES);

    // 0) round weights; init RoPE table
    round_tf32_kernel<<<(QKV_N * DIM / 4 + 255) / 256, 256>>>(w_qkv, wqkv_r, QKV_N * DIM / 4);
    round_tf32_kernel<<<(DIM * DIM / 4 + 255) / 256, 256>>>(w_out, wout_r, DIM * DIM / 4);
    rope_init_kernel<<<1, 1024>>>();

    // 1) LayerNorm + transpose -> g_normed (T, C)
    ln_transpose_kernel<<<TLEN / 32, dim3(32, 32)>>>(x, gamma, beta);

    // 2) QKV GEMM (tf32 mma.sync)
    mma_gemm_nt<false><<<dim3(QKV_N / GBN, TLEN / GBM), 256, GSMEM_BYTES>>>(
        normed, wqkv_r, qkv, nullptr, TLEN, QKV_N, DIM);

    // 3) windowed RoPE attention (tf32 mma.sync) -> g_attn (T, C)
    attn_mma_kernel<<<NWIN * HEADS / AWARPS, AWARPS * 32, ASMEM_BYTES>>>();

    // 4) out = (w_out @ attn^T) + x, written as (C, T)
    mma_gemm_nt<true><<<dim3(TLEN / GBN, DIM / GBM), 256, GSMEM_BYTES>>>(
        wout_r, attn, out, x, DIM, TLEN, DIM);
}

// round 7
// speedup vs baseline: 2.2169x; 1.6862x over previous
#include <cuda_runtime.h>
#include <cuda_fp16.h>
#include <math.h>
#include <stdint.h>

#define DIM     1024
#define TLEN    16384
#define WIN     32
#define DH      64
#define HEADS   16
#define NWIN    (TLEN / WIN)      // 512
#define QKV_N   (3 * DIM)         // 3072

// ---------------- scratch (static device globals; no allocation) ----------------
static __device__ __half g_normed[(size_t)TLEN * DIM];   // (T, C) fp16
static __device__ float  g_qkv[(size_t)TLEN * QKV_N];    // (T, 3C) fp32
static __device__ __half g_attn[(size_t)TLEN * DIM];     // (T, C) fp16
static __device__ __half g_wqkv_h[(size_t)QKV_N * DIM];  // fp16 weights
static __device__ __half g_wout_h[(size_t)DIM * DIM];    // fp16 weights
static __device__ float  g_rope_cos[WIN * 32];
static __device__ float  g_rope_sin[WIN * 32];

// =============================== helpers ===================================
__device__ __forceinline__ uint32_t smem_u32(const void* p) {
    uint32_t a;
    asm("{ .reg .u64 t; cvta.to.shared.u64 t, %1; cvt.u32.u64 %0, t; }" : "=r"(a) : "l"(p));
    return a;
}
__device__ __forceinline__ float rna_tf32(float x) {
    uint32_t r;
    asm("cvt.rna.tf32.f32 %0, %1;" : "=r"(r) : "f"(x));
    return __uint_as_float(r);
}

// =================================================================================
// Kernel 0a: round fp32 -> fp16 weights
// =================================================================================
__global__ void round_fp16_kernel(const float* __restrict__ in, __half* __restrict__ out, int n4)
{
    int i = blockIdx.x * blockDim.x + threadIdx.x;
    if (i < n4) {
        float4 v = *(const float4*)&in[i * 4];
        __half2 h0 = __floats2half2_rn(v.x, v.y);
        __half2 h1 = __floats2half2_rn(v.z, v.w);
        *(__half2*)&out[i * 4]     = h0;
        *(__half2*)&out[i * 4 + 2] = h1;
    }
}

// =================================================================================
// Kernel 0b: RoPE table init
// =================================================================================
__global__ void rope_init_kernel()
{
    int idx = threadIdx.x;
    int n = idx >> 5;
    int i = idx & 31;
    float invf = expf(-logf(10000.f) * (float)i * (1.0f / 32.0f));
    float ang  = (float)n * invf;
    g_rope_cos[idx] = cosf(ang);
    g_rope_sin[idx] = sinf(ang);
}

// =================================================================================
// Kernel 1: LayerNorm over channels + transpose (C,T) -> (T,C), fp16 output
// =================================================================================
__global__ void __launch_bounds__(1024) ln_transpose_kernel(
    const float* __restrict__ x,
    const float* __restrict__ gamma,
    const float* __restrict__ beta)
{
    __shared__ float reds[32][33];
    __shared__ float redq[32][33];
    __shared__ __align__(16) float tile[32][33];
    __shared__ float s_mean[32], s_rstd[32];

    const int tx = threadIdx.x;
    const int ty = threadIdx.y;
    const int t0 = blockIdx.x * 32;

    float cache[32];
    float sum = 0.f, sumsq = 0.f;
    #pragma unroll
    for (int ci = 0; ci < 32; ci++) {
        float v = x[(size_t)(ci * 32 + ty) * TLEN + t0 + tx];
        cache[ci] = v;
        sum += v;
        sumsq += v * v;
    }
    reds[ty][tx] = sum;
    redq[ty][tx] = sumsq;
    __syncthreads();
    for (int s = 16; s > 0; s >>= 1) {
        if (ty < s) {
            reds[ty][tx] += reds[ty + s][tx];
            redq[ty][tx] += redq[ty + s][tx];
        }
        __syncthreads();
    }
    if (ty == 0) {
        float m = reds[0][tx] * (1.0f / DIM);
        float var = redq[0][tx] * (1.0f / DIM) - m * m;
        s_mean[tx] = m;
        s_rstd[tx] = rsqrtf(var + 1e-5f);
    }
    __syncthreads();

    #pragma unroll
    for (int ci = 0; ci < 32; ci++) {
        int c0 = ci * 32;
        float nv = (cache[ci] - s_mean[tx]) * s_rstd[tx] * gamma[c0 + ty] + beta[c0 + ty];
        tile[ty][tx] = nv;
        __syncthreads();
        g_normed[(size_t)(t0 + ty) * DIM + c0 + tx] = __float2half_rn(tile[tx][ty]);
        __syncthreads();
    }
}

// =================================================================================
// Kernel 2: fp16 mma.sync GEMM-NT: C[M,N] = A[M,K] * B[N,K]^T   (+resid)
// BM=BN=128, BK=64 elements (128B rows), 3-stage cp.async, 256 threads,
// 8 warps of 64x32, m16n8k16, fp32 accumulate. Row stride 72 halves (conflict-free).
// =================================================================================
#define GBM 128
#define GBN 128
#define GBK 64
#define GSTAGES 3
#define ROWH 72
#define TILEH (128 * ROWH)
#define STAGEH (2 * TILEH)
#define GSMEM_BYTES (GSTAGES * STAGEH * 2)   // 110592 B

template <bool RESID>
__global__ void __launch_bounds__(256) hgemm_nt(
    const __half* __restrict__ A,
    const __half* __restrict__ B,
    float* __restrict__ C,
    const float* __restrict__ resid,
    int M, int N, int K)
{
    extern __shared__ __half sh[];
    const int tid  = threadIdx.x;
    const int wid  = tid >> 5;
    const int lane = tid & 31;
    const int g = lane >> 2;          // 0..7
    const int t = lane & 3;           // 0..3
    const int m0 = blockIdx.y * GBM;
    const int n0 = blockIdx.x * GBN;
    const int wm = (wid >> 2) * 64;
    const int wn = (wid & 3) * 32;
    const int KC = K / GBK;

    float c[4][4][4];
    #pragma unroll
    for (int mi = 0; mi < 4; mi++)
        #pragma unroll
        for (int ni = 0; ni < 4; ni++)
            #pragma unroll
            for (int j = 0; j < 4; j++) c[mi][ni][j] = 0.f;

    // loader: per tile, 128 rows x 8 chunks of 16B; thread -> 4 chunks per tile
    const int lrow = tid >> 3;                // 0..31
    const int lc8  = (tid & 7) << 3;          // half offset 0..56 (16B chunks)

    #pragma unroll
    for (int s = 0; s < GSTAGES - 1; s++) {
        __half* as = sh + s * STAGEH;
        __half* bs = as + TILEH;
        #pragma unroll
        for (int i = 0; i < 4; i++) {
            int row = lrow + i * 32;
            uint32_t sa = smem_u32(as + row * ROWH + lc8);
            const __half* ga = A + (size_t)(m0 + row) * K + s * GBK + lc8;
            asm volatile("cp.async.cg.shared.global [%0], [%1], 16;" :: "r"(sa), "l"(ga));
            uint32_t sb = smem_u32(bs + row * ROWH + lc8);
            const __half* gb = B + (size_t)(n0 + row) * K + s * GBK + lc8;
            asm volatile("cp.async.cg.shared.global [%0], [%1], 16;" :: "r"(sb), "l"(gb));
        }
        asm volatile("cp.async.commit_group;");
    }

    for (int kc = 0; kc < KC; kc++) {
        if (kc + 1 < KC) asm volatile("cp.async.wait_group 1;");
        else             asm volatile("cp.async.wait_group 0;");
        __syncthreads();

        int nxt = kc + 2;
        if (nxt < KC) {
            int slot = nxt % GSTAGES;
            __half* as = sh + slot * STAGEH;
            __half* bs = as + TILEH;
            #pragma unroll
            for (int i = 0; i < 4; i++) {
                int row = lrow + i * 32;
                uint32_t sa = smem_u32(as + row * ROWH + lc8);
                const __half* ga = A + (size_t)(m0 + row) * K + nxt * GBK + lc8;
                asm volatile("cp.async.cg.shared.global [%0], [%1], 16;" :: "r"(sa), "l"(ga));
                uint32_t sb = smem_u32(bs + row * ROWH + lc8);
                const __half* gb = B + (size_t)(n0 + row) * K + nxt * GBK + lc8;
                asm volatile("cp.async.cg.shared.global [%0], [%1], 16;" :: "r"(sb), "l"(gb));
            }
            asm volatile("cp.async.commit_group;");
        }

        const __half* as = sh + (kc % GSTAGES) * STAGEH;
        const __half* bs = as + TILEH;

        #pragma unroll
        for (int kk = 0; kk < GBK; kk += 16) {
            uint32_t a[4][4], b[4][2];
            #pragma unroll
            for (int mi = 0; mi < 4; mi++) {
                const __half* ap = as + (wm + mi * 16 + g) * ROWH + kk + 2 * t;
                a[mi][0] = *(const uint32_t*)(ap);
                a[mi][1] = *(const uint32_t*)(ap + 8 * ROWH);
                a[mi][2] = *(const uint32_t*)(ap + 8);
                a[mi][3] = *(const uint32_t*)(ap + 8 * ROWH + 8);
            }
            #pragma unroll
            for (int ni = 0; ni < 4; ni++) {
                const __half* bp = bs + (wn + ni * 8 + g) * ROWH + kk + 2 * t;
                b[ni][0] = *(const uint32_t*)(bp);
                b[ni][1] = *(const uint32_t*)(bp + 8);
            }
            #pragma unroll
            for (int mi = 0; mi < 4; mi++)
                #pragma unroll
                for (int ni = 0; ni < 4; ni++)
                    asm volatile(
                        "mma.sync.aligned.m16n8k16.row.col.f32.f16.f16.f32 "
                        "{%0,%1,%2,%3},{%4,%5,%6,%7},{%8,%9},{%0,%1,%2,%3};"
                        : "+f"(c[mi][ni][0]), "+f"(c[mi][ni][1]),
                          "+f"(c[mi][ni][2]), "+f"(c[mi][ni][3])
                        : "r"(a[mi][0]), "r"(a[mi][1]), "r"(a[mi][2]), "r"(a[mi][3]),
                          "r"(b[ni][0]), "r"(b[ni][1]));
        }
    }

    // epilogue: thread (g,t) owns rows (wm+16mi+g, +8), cols (wn+8ni+2t, +1)
    #pragma unroll
    for (int mi = 0; mi < 4; mi++) {
        #pragma unroll
        for (int ni = 0; ni < 4; ni++) {
            size_t r0  = (size_t)(m0 + wm + mi * 16 + g);
            size_t col = (size_t)(n0 + wn + ni * 8 + 2 * t);
            size_t off0 = r0 * N + col;
            size_t off1 = (r0 + 8) * N + col;
            float2 v0 = make_float2(c[mi][ni][0], c[mi][ni][1]);
            float2 v1 = make_float2(c[mi][ni][2], c[mi][ni][3]);
            if (RESID) {
                float2 rv0 = *(const float2*)&resid[off0];
                float2 rv1 = *(const float2*)&resid[off1];
                v0.x += rv0.x; v0.y += rv0.y;
                v1.x += rv1.x; v1.y += rv1.y;
            }
            *(float2*)&C[off0] = v0;
            *(float2*)&C[off1] = v1;
        }
    }
}

// =================================================================================
// Kernel 3: warp-per-(window,head) attention via tf32 mma.sync, fp16 output.
// =================================================================================
#define AWARPS 4
#define ASTRIDE 68
#define AWARP_F (3 * 32 * ASTRIDE)
#define ASMEM_BYTES (AWARPS * AWARP_F * 4)   // 104448 B

__global__ void __launch_bounds__(AWARPS * 32) attn_mma_kernel()
{
    extern __shared__ float as_[];
    const int lane = threadIdx.x & 31;
    const int wid  = threadIdx.x >> 5;
    const int pair = blockIdx.x * AWARPS + wid;
    const int w = pair >> 4;
    const int h = pair & 15;
    const int gr = lane >> 2;
    const int t  = lane & 3;

    float* q = as_ + wid * AWARP_F;
    float* k = q + 32 * ASTRIDE;
    float* v = k + 32 * ASTRIDE;
    float* p = q;

    const float* gbase = g_qkv + (size_t)w * WIN * QKV_N + h * DH;

    #pragma unroll
    for (int it = 0; it < 16; it++) {
        int idx = lane + it * 32;
        int n   = idx >> 4;
        int d4  = (idx & 15) << 2;
        const float* rp = gbase + (size_t)n * QKV_N + d4;
        float4 qa = *(const float4*)rp;
        float4 ka = *(const float4*)(rp + DIM);
        float4 va = *(const float4*)(rp + 2 * DIM);
        *(float4*)&q[n * ASTRIDE + d4] = qa;
        *(float4*)&k[n * ASTRIDE + d4] = ka;
        va.x = rna_tf32(va.x); va.y = rna_tf32(va.y);
        va.z = rna_tf32(va.z); va.w = rna_tf32(va.w);
        *(float4*)&v[n * ASTRIDE + d4] = va;
    }
    __syncwarp();

    #pragma unroll
    for (int it = 0; it < 32; it++) {
        int idx = lane + it * 32;
        int n = idx >> 5;
        int i = idx & 31;
        float c = g_rope_cos[idx];
        float s = g_rope_sin[idx];
        float* qr = q + n * ASTRIDE;
        float* kr = k + n * ASTRIDE;
        float qa = qr[i], qb = qr[i + 32];
        qr[i]      = rna_tf32(qa * c - qb * s);
        qr[i + 32] = rna_tf32(qb * c + qa * s);
        float ka = kr[i], kb = kr[i + 32];
        kr[i]      = rna_tf32(ka * c - kb * s);
        kr[i + 32] = rna_tf32(kb * c + ka * s);
    }
    __syncwarp();

    float s[2][4][4];
    #pragma unroll
    for (int mi = 0; mi < 2; mi++)
        #pragma unroll
        for (int nt = 0; nt < 4; nt++)
            #pragma unroll
            for (int j = 0; j < 4; j++) s[mi][nt][j] = 0.f;

    #pragma unroll
    for (int kk = 0; kk < 64; kk += 8) {
        uint32_t a[2][4], b[4][2];
        #pragma unroll
        for (int mi = 0; mi < 2; mi++) {
            const float* ap = q + (mi * 16 + gr) * ASTRIDE + kk + t;
            a[mi][0] = __float_as_uint(ap[0]);
            a[mi][1] = __float_as_uint(ap[8 * ASTRIDE]);
            a[mi][2] = __float_as_uint(ap[4]);
            a[mi][3] = __float_as_uint(ap[8 * ASTRIDE + 4]);
        }
        #pragma unroll
        for (int nt = 0; nt < 4; nt++) {
            const float* bp = k + (nt * 8 + gr) * ASTRIDE + kk + t;
            b[nt][0] = __float_as_uint(bp[0]);
            b[nt][1] = __float_as_uint(bp[4]);
        }
        #pragma unroll
        for (int mi = 0; mi < 2; mi++)
            #pragma unroll
            for (int nt = 0; nt < 4; nt++)
                asm volatile(
                    "mma.sync.aligned.m16n8k8.row.col.f32.tf32.tf32.f32 "
                    "{%0,%1,%2,%3},{%4,%5,%6,%7},{%8,%9},{%0,%1,%2,%3};"
                    : "+f"(s[mi][nt][0]), "+f"(s[mi][nt][1]),
                      "+f"(s[mi][nt][2]), "+f"(s[mi][nt][3])
                    : "r"(a[mi][0]), "r"(a[mi][1]), "r"(a[mi][2]), "r"(a[mi][3]),
                      "r"(b[nt][0]), "r"(b[nt][1]));
    }
    __syncwarp();

    const float scale = 0.125f;
    #pragma unroll
    for (int mi = 0; mi < 2; mi++) {
        #pragma unroll
        for (int half = 0; half < 2; half++) {
            int row = mi * 16 + gr + 8 * half;
            float e[8];
            float m = -1e30f;
            #pragma unroll
            for (int nt = 0; nt < 4; nt++) {
                e[2 * nt]     = s[mi][nt][2 * half]     * scale;
                e[2 * nt + 1] = s[mi][nt][2 * half + 1] * scale;
                m = fmaxf(m, fmaxf(e[2 * nt], e[2 * nt + 1]));
            }
            m = fmaxf(m, __shfl_xor_sync(0xFFFFFFFFu, m, 1));
            m = fmaxf(m, __shfl_xor_sync(0xFFFFFFFFu, m, 2));
            float sum = 0.f;
            #pragma unroll
            for (int j = 0; j < 8; j++) {
                e[j] = __expf(e[j] - m);
                sum += e[j];
            }
            sum += __shfl_xor_sync(0xFFFFFFFFu, sum, 1);
            sum += __shfl_xor_sync(0xFFFFFFFFu, sum, 2);
            float inv = __fdividef(1.0f, sum);
            float* pr = p + row * ASTRIDE + 2 * t;
            #pragma unroll
            for (int nt = 0; nt < 4; nt++) {
                pr[nt * 8]     = rna_tf32(e[2 * nt]     * inv);
                pr[nt * 8 + 1] = rna_tf32(e[2 * nt + 1] * inv);
            }
        }
    }
    __syncwarp();

    float o[2][8][4];
    #pragma unroll
    for (int mi = 0; mi < 2; mi++)
        #pragma unroll
        for (int nt = 0; nt < 8; nt++)
            #pragma unroll
            for (int j = 0; j < 4; j++) o[mi][nt][j] = 0.f;

    #pragma unroll
    for (int kk = 0; kk < 32; kk += 8) {
        uint32_t a[2][4];
        #pragma unroll
        for (int mi = 0; mi < 2; mi++) {
            const float* ap = p + (mi * 16 + gr) * ASTRIDE + kk + t;
            a[mi][0] = __float_as_uint(ap[0]);
            a[mi][1] = __float_as_uint(ap[8 * ASTRIDE]);
            a[mi][2] = __float_as_uint(ap[4]);
            a[mi][3] = __float_as_uint(ap[8 * ASTRIDE + 4]);
        }
        #pragma unroll
        for (int nt = 0; nt < 8; nt++) {
            uint32_t b0 = __float_as_uint(v[(kk + t) * ASTRIDE + nt * 8 + gr]);
            uint32_t b1 = __float_as_uint(v[(kk + t + 4) * ASTRIDE + nt * 8 + gr]);
            #pragma unroll
            for (int mi = 0; mi < 2; mi++)
                asm volatile(
                    "mma.sync.aligned.m16n8k8.row.col.f32.tf32.tf32.f32 "
                    "{%0,%1,%2,%3},{%4,%5,%6,%7},{%8,%9},{%0,%1,%2,%3};"
                    : "+f"(o[mi][nt][0]), "+f"(o[mi][nt][1]),
                      "+f"(o[mi][nt][2]), "+f"(o[mi][nt][3])
                    : "r"(a[mi][0]), "r"(a[mi][1]), "r"(a[mi][2]), "r"(a[mi][3]),
                      "r"(b0), "r"(b1));
        }
    }

    __half* op = g_attn + (size_t)(w * WIN) * DIM + h * DH;
    #pragma unroll
    for (int mi = 0; mi < 2; mi++) {
        #pragma unroll
        for (int nt = 0; nt < 8; nt++) {
            int row0 = mi * 16 + gr;
            int col  = nt * 8 + 2 * t;
            *(__half2*)&op[(size_t)row0 * DIM + col] =
                __floats2half2_rn(o[mi][nt][0], o[mi][nt][1]);
            *(__half2*)&op[(size_t)(row0 + 8) * DIM + col] =
                __floats2half2_rn(o[mi][nt][2], o[mi][nt][3]);
        }
    }
}

// =================================================================================
// launch
// =================================================================================
extern "C" void kernel_launch(void* const* d_in, const int* in_sizes, int n_in,
                              void* d_out, int out_size)
{
    (void)in_sizes; (void)n_in; (void)out_size;
    const float* x     = (const float*)d_in[0];
    const float* w_qkv = (const float*)d_in[1];
    const float* w_out = (const float*)d_in[2];
    const float* gamma = (const float*)d_in[3];
    const float* beta  = (const float*)d_in[4];
    float* out = (float*)d_out;

    __half *normed, *attn, *wqkv_h, *wout_h;
    float *qkv;
    cudaGetSymbolAddress((void**)&normed, g_normed);
    cudaGetSymbolAddress((void**)&qkv,    g_qkv);
    cudaGetSymbolAddress((void**)&attn,   g_attn);
    cudaGetSymbolAddress((void**)&wqkv_h, g_wqkv_h);
    cudaGetSymbolAddress((void**)&wout_h, g_wout_h);

    cudaFuncSetAttribute(hgemm_nt<false>, cudaFuncAttributeMaxDynamicSharedMemorySize, GSMEM_BYTES);
    cudaFuncSetAttribute(hgemm_nt<true>,  cudaFuncAttributeMaxDynamicSharedMemorySize, GSMEM_BYTES);
    cudaFuncSetAttribute(attn_mma_kernel, cudaFuncAttributeMaxDynamicSharedMemorySize, ASMEM_BYTES);

    // 0) round weights to fp16; init RoPE table
    round_fp16_kernel<<<(QKV_N * DIM / 4 + 255) / 256, 256>>>(w_qkv, wqkv_h, QKV_N * DIM / 4);
    round_fp16_kernel<<<(DIM * DIM / 4 + 255) / 256, 256>>>(w_out, wout_h, DIM * DIM / 4);
    rope_init_kernel<<<1, 1024>>>();

    // 1) LayerNorm + transpose -> g_normed (T, C) fp16
    ln_transpose_kernel<<<TLEN / 32, dim3(32, 32)>>>(x, gamma, beta);

    // 2) QKV GEMM (fp16 mma.sync, fp32 accum): (T,3C) = normed @ w_qkv^T
    hgemm_nt<false><<<dim3(QKV_N / GBN, TLEN / GBM), 256, GSMEM_BYTES>>>(
        normed, wqkv_h, qkv, nullptr, TLEN, QKV_N, DIM);

    // 3) windowed RoPE attention (tf32 mma.sync) -> g_attn (T, C) fp16
    attn_mma_kernel<<<NWIN * HEADS / AWARPS, AWARPS * 32, ASMEM_BYTES>>>();

    // 4) out = (w_out @ attn^T) + x, written as (C, T)
    hgemm_nt<true><<<dim3(TLEN / GBN, DIM / GBM), 256, GSMEM_BYTES>>>(
        wout_h, attn, out, x, DIM, TLEN, DIM);
}

// round 8
// speedup vs baseline: 2.3704x; 1.0692x over previous
#include <cuda_runtime.h>
#include <cuda_fp16.h>
#include <math.h>
#include <stdint.h>

#define DIM     1024
#define TLEN    16384
#define WIN     32
#define DH      64
#define HEADS   16
#define NWIN    (TLEN / WIN)      // 512
#define QKV_N   (3 * DIM)         // 3072

// ---------------- scratch (static device globals; no allocation) ----------------
static __device__ __half g_normed[(size_t)TLEN * DIM];   // (T, C) fp16
static __device__ __half g_qkv[(size_t)TLEN * QKV_N];    // (T, 3C) fp16
static __device__ __half g_attn[(size_t)TLEN * DIM];     // (T, C) fp16
static __device__ __half g_wqkv_h[(size_t)QKV_N * DIM];  // fp16 weights
static __device__ __half g_wout_h[(size_t)DIM * DIM];    // fp16 weights
static __device__ float  g_rope_cos[WIN * 32];
static __device__ float  g_rope_sin[WIN * 32];

// =============================== helpers ===================================
__device__ __forceinline__ uint32_t smem_u32(const void* p) {
    uint32_t a;
    asm("{ .reg .u64 t; cvta.to.shared.u64 t, %1; cvt.u32.u64 %0, t; }" : "=r"(a) : "l"(p));
    return a;
}
__device__ __forceinline__ float rna_tf32(float x) {
    uint32_t r;
    asm("cvt.rna.tf32.f32 %0, %1;" : "=r"(r) : "f"(x));
    return __uint_as_float(r);
}
#define LDMATRIX_X4(r0, r1, r2, r3, addr) \
    asm volatile("ldmatrix.sync.aligned.m8n8.x4.shared.b16 {%0,%1,%2,%3}, [%4];" \
                 : "=r"(r0), "=r"(r1), "=r"(r2), "=r"(r3) : "r"(addr))

// =================================================================================
// Kernel 0a: round fp32 -> fp16 weights
// =================================================================================
__global__ void round_fp16_kernel(const float* __restrict__ in, __half* __restrict__ out, int n4)
{
    int i = blockIdx.x * blockDim.x + threadIdx.x;
    if (i < n4) {
        float4 v = *(const float4*)&in[i * 4];
        *(__half2*)&out[i * 4]     = __floats2half2_rn(v.x, v.y);
        *(__half2*)&out[i * 4 + 2] = __floats2half2_rn(v.z, v.w);
    }
}

// =================================================================================
// Kernel 0b: RoPE table init
// =================================================================================
__global__ void rope_init_kernel()
{
    int idx = threadIdx.x;
    int n = idx >> 5;
    int i = idx & 31;
    float invf = expf(-logf(10000.f) * (float)i * (1.0f / 32.0f));
    float ang  = (float)n * invf;
    g_rope_cos[idx] = cosf(ang);
    g_rope_sin[idx] = sinf(ang);
}

// =================================================================================
// Kernel 1: LayerNorm over channels + transpose (C,T) -> (T,C), fp16 output.
// One smem staging tile (32 tokens x 1024 ch, stride 1026 halves), single sync,
// coalesced uint4 store phase.
// =================================================================================
#define LN_STRIDE 1026
#define LN_SMEM_BYTES (32 * LN_STRIDE * 2)   // 65664

__global__ void __launch_bounds__(1024) ln_transpose_kernel(
    const float* __restrict__ x,
    const float* __restrict__ gamma,
    const float* __restrict__ beta)
{
    extern __shared__ __half st[];
    __shared__ float reds[32][33];
    __shared__ float redq[32][33];
    __shared__ float s_mean[32], s_rstd[32];

    const int tx = threadIdx.x;   // token within tile on load
    const int ty = threadIdx.y;   // channel within chunk
    const int t0 = blockIdx.x * 32;
    const int tid = ty * 32 + tx;

    float cache[32];
    float sum = 0.f, sumsq = 0.f;
    #pragma unroll
    for (int ci = 0; ci < 32; ci++) {
        float v = x[(size_t)(ci * 32 + ty) * TLEN + t0 + tx];
        cache[ci] = v;
        sum += v;
        sumsq += v * v;
    }
    reds[ty][tx] = sum;
    redq[ty][tx] = sumsq;
    __syncthreads();
    for (int s = 16; s > 0; s >>= 1) {
        if (ty < s) {
            reds[ty][tx] += reds[ty + s][tx];
            redq[ty][tx] += redq[ty + s][tx];
        }
        __syncthreads();
    }
    if (ty == 0) {
        float m = reds[0][tx] * (1.0f / DIM);
        float var = redq[0][tx] * (1.0f / DIM) - m * m;
        s_mean[tx] = m;
        s_rstd[tx] = rsqrtf(var + 1e-5f);
    }
    __syncthreads();

    // normalize into fp16 staging tile: thread (tx,ty) owns token tx, channels ci*32+ty
    const float mean = s_mean[tx];
    const float rstd = s_rstd[tx];
    #pragma unroll
    for (int ci = 0; ci < 32; ci++) {
        int c = ci * 32 + ty;
        float nv = (cache[ci] - mean) * rstd * gamma[c] + beta[c];
        st[tx * LN_STRIDE + c] = __float2half_rn(nv);
    }
    __syncthreads();

    // coalesced store: 4096 x 16B, 4 per thread
    const uint32_t stb = smem_u32(st);
    #pragma unroll
    for (int i = 0; i < 4; i++) {
        int idx = tid + i * 1024;          // 0..4095
        int tok = idx >> 7;                // 0..31
        int f4  = idx & 127;               // float4 index within row
        uint32_t sa = stb + (uint32_t)(tok * LN_STRIDE + f4 * 8) * 2;
        uint4 u;
        asm volatile("ld.shared.u32 %0, [%1];"      : "=r"(u.x) : "r"(sa));
        asm volatile("ld.shared.u32 %0, [%1 + 4];"  : "=r"(u.y) : "r"(sa));
        asm volatile("ld.shared.u32 %0, [%1 + 8];"  : "=r"(u.z) : "r"(sa));
        asm volatile("ld.shared.u32 %0, [%1 + 12];" : "=r"(u.w) : "r"(sa));
        *(uint4*)&g_normed[(size_t)(t0 + tok) * DIM + f4 * 8] = u;
    }
}

// =================================================================================
// Kernel 2: fp16 mma.sync GEMM-NT with ldmatrix fragment loads.
// C[M,N] = A[M,K] * B[N,K]^T (+resid). BM=BN=128, BK=64, 3-stage cp.async,
// 256 threads, 8 warps of 64x32, m16n8k16, fp32 accumulate. Row stride 72 halves.
// =================================================================================
#define GBM 128
#define GBN 128
#define GBK 64
#define GSTAGES 3
#define ROWH 72
#define TILEH (128 * ROWH)
#define STAGEH (2 * TILEH)
#define GSMEM_BYTES (GSTAGES * STAGEH * 2)   // 110592 B

template <bool RESID, typename TOUT>
__global__ void __launch_bounds__(256) hgemm_nt(
    const __half* __restrict__ A,
    const __half* __restrict__ B,
    TOUT* __restrict__ C,
    const float* __restrict__ resid,
    int M, int N, int K)
{
    extern __shared__ __half sh[];
    const uint32_t shb = smem_u32(sh);
    const int tid  = threadIdx.x;
    const int wid  = tid >> 5;
    const int lane = tid & 31;
    const int g = lane >> 2;
    const int t = lane & 3;
    const int m0 = blockIdx.y * GBM;
    const int n0 = blockIdx.x * GBN;
    const int wm = (wid >> 2) * 64;
    const int wn = (wid & 3) * 32;
    const int KC = K / GBK;

    // ldmatrix per-lane address components
    const int a_row = wm + (lane & 15);
    const int a_col = (lane >> 4) << 3;                       // 0 or 8
    const int b_row = wn + ((lane >> 4) << 3) + (lane & 7);   // 16-row group select
    const int b_col = ((lane >> 3) & 1) << 3;                 // 0 or 8
    const uint32_t a_off = (uint32_t)(a_row * ROWH + a_col) * 2;
    const uint32_t b_off = (uint32_t)(TILEH + b_row * ROWH + b_col) * 2;

    float c[4][4][4];
    #pragma unroll
    for (int mi = 0; mi < 4; mi++)
        #pragma unroll
        for (int ni = 0; ni < 4; ni++)
            #pragma unroll
            for (int j = 0; j < 4; j++) c[mi][ni][j] = 0.f;

    const int lrow = tid >> 3;
    const int lc8  = (tid & 7) << 3;

    #pragma unroll
    for (int s = 0; s < GSTAGES - 1; s++) {
        __half* as = sh + s * STAGEH;
        __half* bs = as + TILEH;
        #pragma unroll
        for (int i = 0; i < 4; i++) {
            int row = lrow + i * 32;
            uint32_t sa = smem_u32(as + row * ROWH + lc8);
            const __half* ga = A + (size_t)(m0 + row) * K + s * GBK + lc8;
            asm volatile("cp.async.cg.shared.global [%0], [%1], 16;" :: "r"(sa), "l"(ga));
            uint32_t sb = smem_u32(bs + row * ROWH + lc8);
            const __half* gb = B + (size_t)(n0 + row) * K + s * GBK + lc8;
            asm volatile("cp.async.cg.shared.global [%0], [%1], 16;" :: "r"(sb), "l"(gb));
        }
        asm volatile("cp.async.commit_group;");
    }

    for (int kc = 0; kc < KC; kc++) {
        if (kc + 1 < KC) asm volatile("cp.async.wait_group 1;");
        else             asm volatile("cp.async.wait_group 0;");
        __syncthreads();

        int nxt = kc + 2;
        if (nxt < KC) {
            int slot = nxt % GSTAGES;
            __half* as = sh + slot * STAGEH;
            __half* bs = as + TILEH;
            #pragma unroll
            for (int i = 0; i < 4; i++) {
                int row = lrow + i * 32;
                uint32_t sa = smem_u32(as + row * ROWH + lc8);
                const __half* ga = A + (size_t)(m0 + row) * K + nxt * GBK + lc8;
                asm volatile("cp.async.cg.shared.global [%0], [%1], 16;" :: "r"(sa), "l"(ga));
                uint32_t sb = smem_u32(bs + row * ROWH + lc8);
                const __half* gb = B + (size_t)(n0 + row) * K + nxt * GBK + lc8;
                asm volatile("cp.async.cg.shared.global [%0], [%1], 16;" :: "r"(sb), "l"(gb));
            }
            asm volatile("cp.async.commit_group;");
        }

        const uint32_t stg = shb + (uint32_t)((kc % GSTAGES) * STAGEH) * 2;
        const uint32_t abase = stg + a_off;
        const uint32_t bbase = stg + b_off;

        #pragma unroll
        for (int kk = 0; kk < GBK; kk += 16) {
            uint32_t a[4][4], b[4][2];
            #pragma unroll
            for (int mi = 0; mi < 4; mi++) {
                uint32_t aa = abase + (uint32_t)(mi * 16 * ROWH + kk) * 2;
                LDMATRIX_X4(a[mi][0], a[mi][1], a[mi][2], a[mi][3], aa);
            }
            #pragma unroll
            for (int np = 0; np < 2; np++) {
                uint32_t bb = bbase + (uint32_t)(np * 16 * ROWH + kk) * 2;
                LDMATRIX_X4(b[2 * np][0], b[2 * np][1], b[2 * np + 1][0], b[2 * np + 1][1], bb);
            }
            #pragma unroll
            for (int mi = 0; mi < 4; mi++)
                #pragma unroll
                for (int ni = 0; ni < 4; ni++)
                    asm volatile(
                        "mma.sync.aligned.m16n8k16.row.col.f32.f16.f16.f32 "
                        "{%0,%1,%2,%3},{%4,%5,%6,%7},{%8,%9},{%0,%1,%2,%3};"
                        : "+f"(c[mi][ni][0]), "+f"(c[mi][ni][1]),
                          "+f"(c[mi][ni][2]), "+f"(c[mi][ni][3])
                        : "r"(a[mi][0]), "r"(a[mi][1]), "r"(a[mi][2]), "r"(a[mi][3]),
                          "r"(b[ni][0]), "r"(b[ni][1]));
        }
    }

    // epilogue: thread (g,t) owns rows (wm+16mi+g, +8), cols (wn+8ni+2t, +1)
    #pragma unroll
    for (int mi = 0; mi < 4; mi++) {
        #pragma unroll
        for (int ni = 0; ni < 4; ni++) {
            size_t r0  = (size_t)(m0 + wm + mi * 16 + g);
            size_t col = (size_t)(n0 + wn + ni * 8 + 2 * t);
            size_t off0 = r0 * N + col;
            size_t off1 = (r0 + 8) * N + col;
            if constexpr (RESID) {
                float2 rv0 = *(const float2*)&resid[off0];
                float2 rv1 = *(const float2*)&resid[off1];
                float2 v0 = make_float2(c[mi][ni][0] + rv0.x, c[mi][ni][1] + rv0.y);
                float2 v1 = make_float2(c[mi][ni][2] + rv1.x, c[mi][ni][3] + rv1.y);
                *(float2*)&((float*)C)[off0] = v0;
                *(float2*)&((float*)C)[off1] = v1;
            } else {
                *(__half2*)&((__half*)C)[off0] = __floats2half2_rn(c[mi][ni][0], c[mi][ni][1]);
                *(__half2*)&((__half*)C)[off1] = __floats2half2_rn(c[mi][ni][2], c[mi][ni][3]);
            }
        }
    }
}

// =================================================================================
// Kernel 3: warp-per-(window,head) attention via tf32 mma.sync, fp16 in/out.
// =================================================================================
#define AWARPS 4
#define ASTRIDE 68
#define AWARP_F (3 * 32 * ASTRIDE)
#define ASMEM_BYTES (AWARPS * AWARP_F * 4)   // 104448 B

__device__ __forceinline__ void h8_to_f8(uint4 u, float* dst) {
    const __half2* hp = (const __half2*)&u;
    #pragma unroll
    for (int j = 0; j < 4; j++) {
        float2 f = __half22float2(hp[j]);
        dst[2 * j]     = f.x;
        dst[2 * j + 1] = f.y;
    }
}

__global__ void __launch_bounds__(AWARPS * 32) attn_mma_kernel()
{
    extern __shared__ float as_[];
    const int lane = threadIdx.x & 31;
    const int wid  = threadIdx.x >> 5;
    const int pair = blockIdx.x * AWARPS + wid;
    const int w = pair >> 4;
    const int h = pair & 15;
    const int gr = lane >> 2;
    const int t  = lane & 3;

    float* q = as_ + wid * AWARP_F;
    float* k = q + 32 * ASTRIDE;
    float* v = k + 32 * ASTRIDE;
    float* p = q;

    const __half* gbase = g_qkv + (size_t)w * WIN * QKV_N + h * DH;

    // stage Q,K,V from fp16 (fp16 values are exactly tf32-representable)
    #pragma unroll
    for (int it = 0; it < 8; it++) {
        int idx = lane + it * 32;                 // 0..255
        int n   = idx >> 3;
        int d8  = (idx & 7) << 3;
        const __half* rp = gbase + (size_t)n * QKV_N + d8;
        uint4 qa = *(const uint4*)rp;
        uint4 ka = *(const uint4*)(rp + DIM);
        uint4 va = *(const uint4*)(rp + 2 * DIM);
        h8_to_f8(qa, q + n * ASTRIDE + d8);
        h8_to_f8(ka, k + n * ASTRIDE + d8);
        h8_to_f8(va, v + n * ASTRIDE + d8);
    }
    __syncwarp();

    // RoPE + tf32 round on Q,K
    #pragma unroll
    for (int it = 0; it < 32; it++) {
        int idx = lane + it * 32;
        int n = idx >> 5;
        int i = idx & 31;
        float c = g_rope_cos[idx];
        float s = g_rope_sin[idx];
        float* qr = q + n * ASTRIDE;
        float* kr = k + n * ASTRIDE;
        float qa = qr[i], qb = qr[i + 32];
        qr[i]      = rna_tf32(qa * c - qb * s);
        qr[i + 32] = rna_tf32(qb * c + qa * s);
        float ka = kr[i], kb = kr[i + 32];
        kr[i]      = rna_tf32(ka * c - kb * s);
        kr[i + 32] = rna_tf32(kb * c + ka * s);
    }
    __syncwarp();

    float s[2][4][4];
    #pragma unroll
    for (int mi = 0; mi < 2; mi++)
        #pragma unroll
        for (int nt = 0; nt < 4; nt++)
            #pragma unroll
            for (int j = 0; j < 4; j++) s[mi][nt][j] = 0.f;

    #pragma unroll
    for (int kk = 0; kk < 64; kk += 8) {
        uint32_t a[2][4], b[4][2];
        #pragma unroll
        for (int mi = 0; mi < 2; mi++) {
            const float* ap = q + (mi * 16 + gr) * ASTRIDE + kk + t;
            a[mi][0] = __float_as_uint(ap[0]);
            a[mi][1] = __float_as_uint(ap[8 * ASTRIDE]);
            a[mi][2] = __float_as_uint(ap[4]);
            a[mi][3] = __float_as_uint(ap[8 * ASTRIDE + 4]);
        }
        #pragma unroll
        for (int nt = 0; nt < 4; nt++) {
            const float* bp = k + (nt * 8 + gr) * ASTRIDE + kk + t;
            b[nt][0] = __float_as_uint(bp[0]);
            b[nt][1] = __float_as_uint(bp[4]);
        }
        #pragma unroll
        for (int mi = 0; mi < 2; mi++)
            #pragma unroll
            for (int nt = 0; nt < 4; nt++)
                asm volatile(
                    "mma.sync.aligned.m16n8k8.row.col.f32.tf32.tf32.f32 "
                    "{%0,%1,%2,%3},{%4,%5,%6,%7},{%8,%9},{%0,%1,%2,%3};"
                    : "+f"(s[mi][nt][0]), "+f"(s[mi][nt][1]),
                      "+f"(s[mi][nt][2]), "+f"(s[mi][nt][3])
                    : "r"(a[mi][0]), "r"(a[mi][1]), "r"(a[mi][2]), "r"(a[mi][3]),
                      "r"(b[nt][0]), "r"(b[nt][1]));
    }
    __syncwarp();

    const float scale = 0.125f;
    #pragma unroll
    for (int mi = 0; mi < 2; mi++) {
        #pragma unroll
        for (int half = 0; half < 2; half++) {
            int row = mi * 16 + gr + 8 * half;
            float e[8];
            float m = -1e30f;
            #pragma unroll
            for (int nt = 0; nt < 4; nt++) {
                e[2 * nt]     = s[mi][nt][2 * half]     * scale;
                e[2 * nt + 1] = s[mi][nt][2 * half + 1] * scale;
                m = fmaxf(m, fmaxf(e[2 * nt], e[2 * nt + 1]));
            }
            m = fmaxf(m, __shfl_xor_sync(0xFFFFFFFFu, m, 1));
            m = fmaxf(m, __shfl_xor_sync(0xFFFFFFFFu, m, 2));
            float sum = 0.f;
            #pragma unroll
            for (int j = 0; j < 8; j++) {
                e[j] = __expf(e[j] - m);
                sum += e[j];
            }
            sum += __shfl_xor_sync(0xFFFFFFFFu, sum, 1);
            sum += __shfl_xor_sync(0xFFFFFFFFu, sum, 2);
            float inv = __fdividef(1.0f, sum);
            float* pr = p + row * ASTRIDE + 2 * t;
            #pragma unroll
            for (int nt = 0; nt < 4; nt++) {
                pr[nt * 8]     = rna_tf32(e[2 * nt]     * inv);
                pr[nt * 8 + 1] = rna_tf32(e[2 * nt + 1] * inv);
            }
        }
    }
    __syncwarp();

    float o[2][8][4];
    #pragma unroll
    for (int mi = 0; mi < 2; mi++)
        #pragma unroll
        for (int nt = 0; nt < 8; nt++)
            #pragma unroll
            for (int j = 0; j < 4; j++) o[mi][nt][j] = 0.f;

    #pragma unroll
    for (int kk = 0; kk < 32; kk += 8) {
        uint32_t a[2][4];
        #pragma unroll
        for (int mi = 0; mi < 2; mi++) {
            const float* ap = p + (mi * 16 + gr) * ASTRIDE + kk + t;
            a[mi][0] = __float_as_uint(ap[0]);
            a[mi][1] = __float_as_uint(ap[8 * ASTRIDE]);
            a[mi][2] = __float_as_uint(ap[4]);
            a[mi][3] = __float_as_uint(ap[8 * ASTRIDE + 4]);
        }
        #pragma unroll
        for (int nt = 0; nt < 8; nt++) {
            uint32_t b0 = __float_as_uint(v[(kk + t) * ASTRIDE + nt * 8 + gr]);
            uint32_t b1 = __float_as_uint(v[(kk + t + 4) * ASTRIDE + nt * 8 + gr]);
            #pragma unroll
            for (int mi = 0; mi < 2; mi++)
                asm volatile(
                    "mma.sync.aligned.m16n8k8.row.col.f32.tf32.tf32.f32 "
                    "{%0,%1,%2,%3},{%4,%5,%6,%7},{%8,%9},{%0,%1,%2,%3};"
                    : "+f"(o[mi][nt][0]), "+f"(o[mi][nt][1]),
                      "+f"(o[mi][nt][2]), "+f"(o[mi][nt][3])
                    : "r"(a[mi][0]), "r"(a[mi][1]), "r"(a[mi][2]), "r"(a[mi][3]),
                      "r"(b0), "r"(b1));
        }
    }

    __half* op = g_attn + (size_t)(w * WIN) * DIM + h * DH;
    #pragma unroll
    for (int mi = 0; mi < 2; mi++) {
        #pragma unroll
        for (int nt = 0; nt < 8; nt++) {
            int row0 = mi * 16 + gr;
            int col  = nt * 8 + 2 * t;
            *(__half2*)&op[(size_t)row0 * DIM + col] =
                __floats2half2_rn(o[mi][nt][0], o[mi][nt][1]);
            *(__half2*)&op[(size_t)(row0 + 8) * DIM + col] =
                __floats2half2_rn(o[mi][nt][2], o[mi][nt][3]);
        }
    }
}

// =================================================================================
// launch
// =================================================================================
extern "C" void kernel_launch(void* const* d_in, const int* in_sizes, int n_in,
                              void* d_out, int out_size)
{
    (void)in_sizes; (void)n_in; (void)out_size;
    const float* x     = (const float*)d_in[0];
    const float* w_qkv = (const float*)d_in[1];
    const float* w_out = (const float*)d_in[2];
    const float* gamma = (const float*)d_in[3];
    const float* beta  = (const float*)d_in[4];
    float* out = (float*)d_out;

    __half *normed, *qkv, *attn, *wqkv_h, *wout_h;
    cudaGetSymbolAddress((void**)&normed, g_normed);
    cudaGetSymbolAddress((void**)&qkv,    g_qkv);
    cudaGetSymbolAddress((void**)&attn,   g_attn);
    cudaGetSymbolAddress((void**)&wqkv_h, g_wqkv_h);
    cudaGetSymbolAddress((void**)&wout_h, g_wout_h);

    cudaFuncSetAttribute((const void*)hgemm_nt<false, __half>,
                         cudaFuncAttributeMaxDynamicSharedMemorySize, GSMEM_BYTES);
    cudaFuncSetAttribute((const void*)hgemm_nt<true, float>,
                         cudaFuncAttributeMaxDynamicSharedMemorySize, GSMEM_BYTES);
    cudaFuncSetAttribute((const void*)attn_mma_kernel,
                         cudaFuncAttributeMaxDynamicSharedMemorySize, ASMEM_BYTES);
    cudaFuncSetAttribute((const void*)ln_transpose_kernel,
                         cudaFuncAttributeMaxDynamicSharedMemorySize, LN_SMEM_BYTES);

    // 0) round weights to fp16; init RoPE table
    round_fp16_kernel<<<(QKV_N * DIM / 4 + 255) / 256, 256>>>(w_qkv, wqkv_h, QKV_N * DIM / 4);
    round_fp16_kernel<<<(DIM * DIM / 4 + 255) / 256, 256>>>(w_out, wout_h, DIM * DIM / 4);
    rope_init_kernel<<<1, 1024>>>();

    // 1) LayerNorm + transpose -> g_normed (T, C) fp16
    ln_transpose_kernel<<<TLEN / 32, dim3(32, 32), LN_SMEM_BYTES>>>(x, gamma, beta);

    // 2) QKV GEMM (fp16 mma.sync + ldmatrix): (T,3C) = normed @ w_qkv^T, fp16 out
    hgemm_nt<false, __half><<<dim3(QKV_N / GBN, TLEN / GBM), 256, GSMEM_BYTES>>>(
        normed, wqkv_h, qkv, nullptr, TLEN, QKV_N, DIM);

    // 3) windowed RoPE attention (tf32 mma.sync) -> g_attn (T, C) fp16
    attn_mma_kernel<<<NWIN * HEADS / AWARPS, AWARPS * 32, ASMEM_BYTES>>>();

    // 4) out = (w_out @ attn^T) + x, written as (C, T) fp32
    hgemm_nt<true, float><<<dim3(TLEN / GBN, DIM / GBM), 256, GSMEM_BYTES>>>(
        wout_h, attn, out, x, DIM, TLEN, DIM);
}